// round 6
// baseline (speedup 1.0000x reference)
#include <cuda_runtime.h>
#include <cuda_bf16.h>
#include <cstdint>

#define H  1024
#define NH 16
#define HD 64
#define BB 2
#define SS 2048
#define T  (BB * SS)      // 4096
#define K3 (3 * H)        // 3072
#define KW 512            // K dim in bf16x2 words (H/2)

// ---- scratch: referenced ONLY from device code (host arg = shadow bug!) ----
__device__ uint32_t g_xnb[(size_t)T * KW];            // LN output, bf16x2
__device__ uint32_t g_wqkv[(size_t)K3 * KW];          // W_qkv bf16x2
__device__ uint32_t g_wout[(size_t)H * KW];           // W_out bf16x2
__device__ uint32_t g_q[(size_t)32 * SS * (HD / 2)];  // [bh][s][d/2]
__device__ uint32_t g_k[(size_t)32 * SS * (HD / 2)];
__device__ __nv_bfloat16 g_vt[(size_t)32 * HD * SS];  // [bh][d][s]  (V transposed)
__device__ uint32_t g_ctxb[(size_t)T * KW];           // ctx bf16x2

// ============================================================
// helpers
// ============================================================
__device__ __forceinline__ uint32_t bf2(float lo, float hi) {
    uint32_t r;
    asm("cvt.rn.bf16x2.f32 %0, %1, %2;" : "=r"(r) : "f"(hi), "f"(lo));
    return r;
}
__device__ __forceinline__ void mma_bf16(float4& c, const uint32_t a[4], uint32_t b0, uint32_t b1) {
    asm volatile(
        "mma.sync.aligned.m16n8k16.row.col.f32.bf16.bf16.f32 "
        "{%0,%1,%2,%3}, {%4,%5,%6,%7}, {%8,%9}, {%0,%1,%2,%3};"
        : "+f"(c.x), "+f"(c.y), "+f"(c.z), "+f"(c.w)
        : "r"(a[0]), "r"(a[1]), "r"(a[2]), "r"(a[3]), "r"(b0), "r"(b1));
}
__device__ __forceinline__ uint32_t smaddr(const void* p) {
    return (uint32_t)__cvta_generic_to_shared(p);
}
__device__ __forceinline__ void cp16(uint32_t dst, const void* src) {
    asm volatile("cp.async.cg.shared.global [%0], [%1], 16;" :: "r"(dst), "l"(src));
}
#define CP_COMMIT() asm volatile("cp.async.commit_group;")
#define CP_WAIT(n)  asm volatile("cp.async.wait_group %0;" :: "n"(n))
__device__ __forceinline__ void ldsm4(uint32_t* r, uint32_t a) {
    asm volatile("ldmatrix.sync.aligned.m8n8.x4.shared.b16 {%0,%1,%2,%3}, [%4];"
                 : "=r"(r[0]), "=r"(r[1]), "=r"(r[2]), "=r"(r[3]) : "r"(a));
}

// ============================================================
// weight fp32 -> bf16x2 converter
// ============================================================
__global__ __launch_bounds__(256) void tobf(const float* __restrict__ src, int which, int nwords) {
    uint32_t* dst = which ? g_wout : g_wqkv;
    int i = blockIdx.x * 256 + threadIdx.x;
    if (i < nwords) dst[i] = bf2(src[2 * i], src[2 * i + 1]);
}

// ============================================================
// LayerNorm -> bf16x2 words
// ============================================================
__global__ __launch_bounds__(256) void ln_kernel(const float* __restrict__ x,
                                                 const float* __restrict__ gamma,
                                                 const float* __restrict__ beta) {
    int row = blockIdx.x;
    int tid = threadIdx.x;
    float4 v = ((const float4*)(x + (size_t)row * H))[tid];
    float s  = v.x + v.y + v.z + v.w;
    float ss = v.x * v.x + v.y * v.y + v.z * v.z + v.w * v.w;
#pragma unroll
    for (int off = 16; off > 0; off >>= 1) {
        s  += __shfl_xor_sync(0xffffffffu, s, off);
        ss += __shfl_xor_sync(0xffffffffu, ss, off);
    }
    __shared__ float red[16];
    int warp = tid >> 5, lane = tid & 31;
    if (lane == 0) { red[warp] = s; red[8 + warp] = ss; }
    __syncthreads();
    float ts = 0.f, tss = 0.f;
#pragma unroll
    for (int w = 0; w < 8; w++) { ts += red[w]; tss += red[8 + w]; }
    float mu   = ts * (1.0f / H);
    float var  = tss * (1.0f / H) - mu * mu;
    float rstd = rsqrtf(var + 1e-5f);
    float4 g  = ((const float4*)gamma)[tid];
    float4 bt = ((const float4*)beta)[tid];
    float ox = (v.x - mu) * rstd * g.x + bt.x;
    float oy = (v.y - mu) * rstd * g.y + bt.y;
    float oz = (v.z - mu) * rstd * g.z + bt.z;
    float ow = (v.w - mu) * rstd * g.w + bt.w;
    g_xnb[(size_t)row * KW + tid * 2 + 0] = bf2(ox, oy);
    g_xnb[(size_t)row * KW + tid * 2 + 1] = bf2(oz, ow);
}

// ============================================================
// Pipelined bf16 GEMM: 128x128 tile, BK=64, 2-stage cp.async, ldmatrix.
// smem row stride 36 words (== 4 mod 32 -> conflict-free ldmatrix).
// MODE 0: A=g_xnb, B=g_wqkv, epilogue -> g_q / g_k (bf16x2) / g_vt (bf16 T)
// MODE 1: A=g_ctxb, B=g_wout, epilogue -> fp32 out (+bias+resid)
// ============================================================
#define SGA 36
#define TILE_W (128 * SGA)   // words per tile buffer

template <int MODE>
__global__ __launch_bounds__(256, 2) void gemm_bf16(const float* __restrict__ bias,
                                                    const float* __restrict__ resid,
                                                    float* __restrict__ outp) {
    extern __shared__ uint32_t smw[];
    uint32_t* As = smw;                  // [2][TILE_W]
    uint32_t* Bs = smw + 2 * TILE_W;
    const uint32_t* Ag = (MODE == 0) ? g_xnb : g_ctxb;
    const uint32_t* Bg = (MODE == 0) ? g_wqkv : g_wout;

    int tid = threadIdx.x;
    int lane = tid & 31;
    int warp = tid >> 5;
    int wm = warp >> 2, wn = warp & 3;
    int g = lane >> 2, t = lane & 3;
    int m0 = blockIdx.y * 128;
    int n0 = blockIdx.x * 128;

    int crow = tid >> 3;          // staging: chunk row base
    int coff = (tid & 7) * 4;     // word offset within row (16B units *4)

    float4 acc[4][4];
#pragma unroll
    for (int i = 0; i < 4; i++)
#pragma unroll
        for (int j = 0; j < 4; j++) acc[i][j] = make_float4(0.f, 0.f, 0.f, 0.f);

    uint32_t as_sm = smaddr(As), bs_sm = smaddr(Bs);

    auto issue = [&](int s) {
        uint32_t ab = as_sm + (s & 1) * (TILE_W * 4);
        uint32_t bb = bs_sm + (s & 1) * (TILE_W * 4);
        int k0w = s * 32;
#pragma unroll
        for (int i = 0; i < 4; i++) {
            int row = crow + i * 32;
            cp16(ab + (row * SGA + coff) * 4, Ag + (size_t)(m0 + row) * KW + k0w + coff);
            cp16(bb + (row * SGA + coff) * 4, Bg + (size_t)(n0 + row) * KW + k0w + coff);
        }
    };

    issue(0);
    CP_COMMIT();

    const int NS = H / 64;   // 16 stages
    for (int s = 0; s < NS; s++) {
        if (s > 0) __syncthreads();
        if (s + 1 < NS) {
            issue(s + 1);
            CP_COMMIT();
            CP_WAIT(1);
        } else {
            CP_WAIT(0);
        }
        __syncthreads();

        uint32_t ab = as_sm + (s & 1) * (TILE_W * 4);
        uint32_t bb = bs_sm + (s & 1) * (TILE_W * 4);
#pragma unroll
        for (int kw = 0; kw < 32; kw += 8) {
            uint32_t af[4][4];
#pragma unroll
            for (int im = 0; im < 4; im++)
                ldsm4(af[im], ab + ((wm * 64 + im * 16 + (lane & 15)) * SGA + kw) * 4 + (lane >> 4) * 16);
            uint32_t bq[2][4];
#pragma unroll
            for (int p = 0; p < 2; p++)
                ldsm4(bq[p], bb + ((wn * 32 + p * 16 + (lane & 15)) * SGA + kw) * 4 + (lane >> 4) * 16);
#pragma unroll
            for (int im = 0; im < 4; im++)
#pragma unroll
                for (int jn = 0; jn < 4; jn++)
                    mma_bf16(acc[im][jn], af[im], bq[jn >> 1][jn & 1], bq[jn >> 1][(jn & 1) + 2]);
        }
    }

    // epilogue
#pragma unroll
    for (int im = 0; im < 4; im++) {
        int rlo = m0 + wm * 64 + im * 16 + g;
#pragma unroll
        for (int jn = 0; jn < 4; jn++) {
            int n = n0 + wn * 32 + jn * 8 + 2 * t;
            float b0 = bias[n], b1 = bias[n + 1];
#pragma unroll
            for (int h = 0; h < 2; h++) {
                int m = h ? (rlo + 8) : rlo;
                float vx = (h ? acc[im][jn].z : acc[im][jn].x) + b0;
                float vy = (h ? acc[im][jn].w : acc[im][jn].y) + b1;
                if (MODE == 0) {
                    int c = n >> 10;
                    int rem = n & 1023;
                    int hh = rem >> 6;
                    int d = rem & 63;
                    int bb2 = m >> 11;
                    int sIdx = m & 2047;
                    int bh = bb2 * NH + hh;
                    if (c == 0) {
                        g_q[((size_t)bh * SS + sIdx) * (HD / 2) + (d >> 1)] = bf2(vx, vy);
                    } else if (c == 1) {
                        g_k[((size_t)bh * SS + sIdx) * (HD / 2) + (d >> 1)] = bf2(vx, vy);
                    } else {
                        g_vt[((size_t)bh * HD + d) * SS + sIdx]     = __float2bfloat16(vx);
                        g_vt[((size_t)bh * HD + d + 1) * SS + sIdx] = __float2bfloat16(vy);
                    }
                } else {
                    size_t idx = (size_t)m * H + n;
                    float2 hv = *(const float2*)(resid + idx);
                    *(float2*)(outp + idx) = make_float2(vx + hv.x, vy + hv.y);
                }
            }
        }
    }
}

// ============================================================
// Flash attention: bf16 mma, register-resident P, cp.async K/V pipeline.
// smem: Qs[128][36w], Ks[2][128][36w], Vt[2][64][68w]
// warp w owns q-rows [w*16, w*16+16) x full n/d extent.
// ============================================================
#define SQW 36
#define SVW 68
#define QTW (128 * SQW)    // 4608 words
#define VTW (64 * SVW)     // 4352 words
#define ATTN_SMEM_BYTES ((QTW * 3 + VTW * 2) * 4)

__global__ __launch_bounds__(256, 1) void attn_kernel() {
    extern __shared__ uint32_t sm[];
    uint32_t* Qs = sm;
    uint32_t* Ks = sm + QTW;            // 2 stages
    uint32_t* Vt = sm + 3 * QTW;        // 2 stages

    int tid = threadIdx.x;
    int lane = tid & 31;
    int warp = tid >> 5;
    int g = lane >> 2, t = lane & 3;
    int bh = blockIdx.y;
    int m0 = blockIdx.x * 128;

    uint32_t qs_sm = smaddr(Qs), ks_sm = smaddr(Ks), vt_sm = smaddr(Vt);

    int crow = tid >> 3;          // K/Q staging rows
    int coff = (tid & 7) * 4;
    int vrow = tid >> 4;          // V staging rows
    int voff = (tid & 15) * 4;

    const uint32_t* qg = g_q + (size_t)bh * SS * (HD / 2);
    const uint32_t* kg = g_k + (size_t)bh * SS * (HD / 2);
    const __nv_bfloat16* vg = g_vt + (size_t)bh * HD * SS;

    auto issueKV = [&](int s) {
        uint32_t kb = ks_sm + (s & 1) * (QTW * 4);
        uint32_t vb = vt_sm + (s & 1) * (VTW * 4);
        int kv = s * 128;
#pragma unroll
        for (int i = 0; i < 4; i++) {
            int row = crow + i * 32;
            cp16(kb + (row * SQW + coff) * 4, kg + (size_t)(kv + row) * (HD / 2) + coff);
        }
#pragma unroll
        for (int i = 0; i < 4; i++) {
            int row = vrow + i * 16;
            cp16(vb + (row * SVW + voff) * 4, vg + (size_t)row * SS + kv + voff * 2);
        }
    };

    // prologue: Q + stage 0 in one group
#pragma unroll
    for (int i = 0; i < 4; i++) {
        int row = crow + i * 32;
        cp16(qs_sm + (row * SQW + coff) * 4, qg + (size_t)(m0 + row) * (HD / 2) + coff);
    }
    issueKV(0);
    CP_COMMIT();

    uint32_t af_q[4][4];   // Q fragments, loaded once
    float m0s = -1e30f, m1s = -1e30f;
    float l0 = 0.f, l1 = 0.f;
    float4 oacc[8];
#pragma unroll
    for (int jd = 0; jd < 8; jd++) oacc[jd] = make_float4(0.f, 0.f, 0.f, 0.f);

    const int NS = SS / 128;   // 16
    for (int s = 0; s < NS; s++) {
        if (s > 0) __syncthreads();
        if (s + 1 < NS) {
            issueKV(s + 1);
            CP_COMMIT();
            CP_WAIT(1);
        } else {
            CP_WAIT(0);
        }
        __syncthreads();

        if (s == 0) {
#pragma unroll
            for (int ks = 0; ks < 4; ks++)
                ldsm4(af_q[ks], qs_sm + ((warp * 16 + (lane & 15)) * SQW + ks * 8) * 4 + (lane >> 4) * 16);
        }

        uint32_t kb = ks_sm + (s & 1) * (QTW * 4);
        uint32_t vb = vt_sm + (s & 1) * (VTW * 4);

        // S = Q K^T : m16 x n128, k=64
        float4 sc[16];
#pragma unroll
        for (int jn = 0; jn < 16; jn++) sc[jn] = make_float4(0.f, 0.f, 0.f, 0.f);
#pragma unroll
        for (int ks = 0; ks < 4; ks++) {
            uint32_t bq[8][4];
#pragma unroll
            for (int p = 0; p < 8; p++)
                ldsm4(bq[p], kb + ((p * 16 + (lane & 15)) * SQW + ks * 8) * 4 + (lane >> 4) * 16);
#pragma unroll
            for (int p = 0; p < 8; p++)
#pragma unroll
                for (int q = 0; q < 2; q++)
                    mma_bf16(sc[2 * p + q], af_q[ks], bq[p][q], bq[p][q + 2]);
        }

        // warp-local online softmax
        float rm0 = -1e30f, rm1 = -1e30f;
#pragma unroll
        for (int jn = 0; jn < 16; jn++) {
            sc[jn].x *= 0.125f; sc[jn].y *= 0.125f;
            sc[jn].z *= 0.125f; sc[jn].w *= 0.125f;
            rm0 = fmaxf(rm0, fmaxf(sc[jn].x, sc[jn].y));
            rm1 = fmaxf(rm1, fmaxf(sc[jn].z, sc[jn].w));
        }
        rm0 = fmaxf(rm0, __shfl_xor_sync(0xffffffffu, rm0, 1));
        rm0 = fmaxf(rm0, __shfl_xor_sync(0xffffffffu, rm0, 2));
        rm1 = fmaxf(rm1, __shfl_xor_sync(0xffffffffu, rm1, 1));
        rm1 = fmaxf(rm1, __shfl_xor_sync(0xffffffffu, rm1, 2));
        float nm0 = fmaxf(m0s, rm0), nm1 = fmaxf(m1s, rm1);
        float a0 = __expf(m0s - nm0), a1 = __expf(m1s - nm1);
        m0s = nm0; m1s = nm1;
        float rs0 = 0.f, rs1 = 0.f;
#pragma unroll
        for (int jn = 0; jn < 16; jn++) {
            sc[jn].x = __expf(sc[jn].x - nm0);
            sc[jn].y = __expf(sc[jn].y - nm0);
            sc[jn].z = __expf(sc[jn].z - nm1);
            sc[jn].w = __expf(sc[jn].w - nm1);
            rs0 += sc[jn].x + sc[jn].y;
            rs1 += sc[jn].z + sc[jn].w;
        }
        rs0 += __shfl_xor_sync(0xffffffffu, rs0, 1);
        rs0 += __shfl_xor_sync(0xffffffffu, rs0, 2);
        rs1 += __shfl_xor_sync(0xffffffffu, rs1, 1);
        rs1 += __shfl_xor_sync(0xffffffffu, rs1, 2);
        l0 = l0 * a0 + rs0;
        l1 = l1 * a1 + rs1;
#pragma unroll
        for (int jd = 0; jd < 8; jd++) {
            oacc[jd].x *= a0; oacc[jd].y *= a0;
            oacc[jd].z *= a1; oacc[jd].w *= a1;
        }

        // O += P V : P stays in registers (C-frag layout == A-frag layout)
#pragma unroll
        for (int ks = 0; ks < 8; ks++) {
            uint32_t ap[4];
            ap[0] = bf2(sc[2 * ks].x, sc[2 * ks].y);
            ap[1] = bf2(sc[2 * ks].z, sc[2 * ks].w);
            ap[2] = bf2(sc[2 * ks + 1].x, sc[2 * ks + 1].y);
            ap[3] = bf2(sc[2 * ks + 1].z, sc[2 * ks + 1].w);
            uint32_t bq[4][4];
#pragma unroll
            for (int p = 0; p < 4; p++)
                ldsm4(bq[p], vb + ((p * 16 + (lane & 15)) * SVW + ks * 8) * 4 + (lane >> 4) * 16);
#pragma unroll
            for (int p = 0; p < 4; p++)
#pragma unroll
                for (int q = 0; q < 2; q++)
                    mma_bf16(oacc[2 * p + q], ap, bq[p][q], bq[p][q + 2]);
        }
    }

    // finalize -> g_ctxb bf16x2: ctx[t, hh*64 + d]
    int b = bh >> 4, hh = bh & 15;
    float inv0 = 1.0f / l0, inv1 = 1.0f / l1;
    size_t t0 = (size_t)(b * SS + m0 + warp * 16 + g);
    size_t t1 = t0 + 8;
#pragma unroll
    for (int jd = 0; jd < 8; jd++) {
        int w = hh * 32 + jd * 4 + t;
        g_ctxb[t0 * KW + w] = bf2(oacc[jd].x * inv0, oacc[jd].y * inv0);
        g_ctxb[t1 * KW + w] = bf2(oacc[jd].z * inv1, oacc[jd].w * inv1);
    }
}

// ============================================================
extern "C" void kernel_launch(void* const* d_in, const int* in_sizes, int n_in,
                              void* d_out, int out_size) {
    const float* hidden = (const float*)d_in[0];
    const float* gamma  = (const float*)d_in[1];
    const float* beta   = (const float*)d_in[2];
    const float* Wqkv   = (const float*)d_in[3];
    const float* bqkv   = (const float*)d_in[4];
    const float* Wout   = (const float*)d_in[5];
    const float* bout   = (const float*)d_in[6];
    float* out = (float*)d_out;

    tobf<<<(K3 * KW) / 256, 256>>>(Wqkv, 0, K3 * KW);
    tobf<<<(H * KW) / 256, 256>>>(Wout, 1, H * KW);
    ln_kernel<<<T, 256>>>(hidden, gamma, beta);

    const int gemm_smem = 4 * TILE_W * 4;
    cudaFuncSetAttribute(gemm_bf16<0>, cudaFuncAttributeMaxDynamicSharedMemorySize, gemm_smem);
    cudaFuncSetAttribute(gemm_bf16<1>, cudaFuncAttributeMaxDynamicSharedMemorySize, gemm_smem);
    cudaFuncSetAttribute(attn_kernel, cudaFuncAttributeMaxDynamicSharedMemorySize, ATTN_SMEM_BYTES);

    dim3 g1(K3 / 128, T / 128);
    gemm_bf16<0><<<g1, 256, gemm_smem>>>(bqkv, nullptr, nullptr);

    attn_kernel<<<dim3(SS / 128, BB * NH), 256, ATTN_SMEM_BYTES>>>();

    dim3 g2(H / 128, T / 128);
    gemm_bf16<1><<<g2, 256, gemm_smem>>>(bout, hidden, out);
}

// round 8
// speedup vs baseline: 1.1602x; 1.1602x over previous
#include <cuda_runtime.h>
#include <cuda_bf16.h>
#include <cstdint>

#define H  1024
#define NH 16
#define HD 64
#define BB 2
#define SS 2048
#define T  (BB * SS)      // 4096
#define K3 (3 * H)        // 3072
#define KWH 512           // H in bf16x2 words

// ---- scratch: referenced ONLY from device code (host arg = shadow bug!) ----
__device__ float g_qkv[(size_t)3 * BB * NH * SS * HD];   // fp32 [3][B][NH][S][HD]
__device__ uint32_t g_xnb[(size_t)T * KWH];              // LN out bf16x2
__device__ uint32_t g_wqkv[(size_t)K3 * KWH];            // W_qkv bf16x2
__device__ uint32_t g_wout[(size_t)H * KWH];             // W_out bf16x2
__device__ uint32_t g_ctxb[(size_t)T * KWH];             // ctx bf16x2

// ============================================================
// helpers
// ============================================================
__device__ __forceinline__ uint32_t bf2(float lo, float hi) {
    uint32_t r;
    asm("cvt.rn.bf16x2.f32 %0, %1, %2;" : "=r"(r) : "f"(hi), "f"(lo));
    return r;
}
__device__ __forceinline__ void mma_bf16(float4& c, const uint32_t a[4], uint32_t b0, uint32_t b1) {
    asm volatile(
        "mma.sync.aligned.m16n8k16.row.col.f32.bf16.bf16.f32 "
        "{%0,%1,%2,%3}, {%4,%5,%6,%7}, {%8,%9}, {%0,%1,%2,%3};"
        : "+f"(c.x), "+f"(c.y), "+f"(c.z), "+f"(c.w)
        : "r"(a[0]), "r"(a[1]), "r"(a[2]), "r"(a[3]), "r"(b0), "r"(b1));
}
__device__ __forceinline__ uint32_t smaddr(const void* p) {
    return (uint32_t)__cvta_generic_to_shared(p);
}
__device__ __forceinline__ void cp16(uint32_t dst, const void* src) {
    asm volatile("cp.async.cg.shared.global [%0], [%1], 16;" :: "r"(dst), "l"(src));
}
#define CP_COMMIT() asm volatile("cp.async.commit_group;")
#define CP_WAIT(n)  asm volatile("cp.async.wait_group %0;" :: "n"(n))
__device__ __forceinline__ void ldsm4(uint32_t* r, uint32_t a) {
    asm volatile("ldmatrix.sync.aligned.m8n8.x4.shared.b16 {%0,%1,%2,%3}, [%4];"
                 : "=r"(r[0]), "=r"(r[1]), "=r"(r[2]), "=r"(r[3]) : "r"(a));
}

// ============================================================
// weight fp32 -> bf16x2
// ============================================================
__global__ __launch_bounds__(256) void tobf(const float* __restrict__ src, int which, int nwords) {
    uint32_t* dst = which ? g_wout : g_wqkv;
    int i = blockIdx.x * 256 + threadIdx.x;
    if (i < nwords) dst[i] = bf2(src[2 * i], src[2 * i + 1]);
}

// ============================================================
// LayerNorm -> bf16x2 words
// ============================================================
__global__ __launch_bounds__(256) void ln_kernel(const float* __restrict__ x,
                                                 const float* __restrict__ gamma,
                                                 const float* __restrict__ beta) {
    int row = blockIdx.x;
    int tid = threadIdx.x;
    float4 v = ((const float4*)(x + (size_t)row * H))[tid];
    float s  = v.x + v.y + v.z + v.w;
    float ss = v.x * v.x + v.y * v.y + v.z * v.z + v.w * v.w;
#pragma unroll
    for (int off = 16; off > 0; off >>= 1) {
        s  += __shfl_xor_sync(0xffffffffu, s, off);
        ss += __shfl_xor_sync(0xffffffffu, ss, off);
    }
    __shared__ float red[16];
    int warp = tid >> 5, lane = tid & 31;
    if (lane == 0) { red[warp] = s; red[8 + warp] = ss; }
    __syncthreads();
    float ts = 0.f, tss = 0.f;
#pragma unroll
    for (int w = 0; w < 8; w++) { ts += red[w]; tss += red[8 + w]; }
    float mu   = ts * (1.0f / H);
    float var  = tss * (1.0f / H) - mu * mu;
    float rstd = rsqrtf(var + 1e-5f);
    float4 g  = ((const float4*)gamma)[tid];
    float4 bt = ((const float4*)beta)[tid];
    float ox = (v.x - mu) * rstd * g.x + bt.x;
    float oy = (v.y - mu) * rstd * g.y + bt.y;
    float oz = (v.z - mu) * rstd * g.z + bt.z;
    float ow = (v.w - mu) * rstd * g.w + bt.w;
    g_xnb[(size_t)row * KWH + tid * 2 + 0] = bf2(ox, oy);
    g_xnb[(size_t)row * KWH + tid * 2 + 1] = bf2(oz, ow);
}

// ============================================================
// Big-warp-tile bf16 GEMM: CTA 128x256, BK=64, warp tile 64x64.
// 2-stage cp.async, ldmatrix fragments, padded stride 36 words.
// MODE 0: A=g_xnb, B=g_wqkv -> fp32 g_qkv (+bias, [3][B][NH][S][HD] remap)
// MODE 1: A=g_ctxb, B=g_wout -> fp32 out (+bias+resid)
// ============================================================
#define SAW 36
#define ATW (128 * SAW)      // A tile words
#define BTW (256 * SAW)      // B tile words
#define GEMM_SMEM ((2 * ATW + 2 * BTW) * 4)   // 110592 B

template <int MODE>
__global__ __launch_bounds__(256, 1) void gemm_bf16(const float* __restrict__ bias,
                                                    const float* __restrict__ resid,
                                                    float* __restrict__ outp) {
    extern __shared__ uint32_t smw[];
    uint32_t* As = smw;                 // [2][ATW]
    uint32_t* Bs = smw + 2 * ATW;       // [2][BTW]
    const uint32_t* Ag = (MODE == 0) ? g_xnb : g_ctxb;
    const uint32_t* Bg = (MODE == 0) ? g_wqkv : g_wout;

    int tid = threadIdx.x;
    int lane = tid & 31;
    int warp = tid >> 5;
    int wm = warp >> 2, wn = warp & 3;    // wm 0..1 (64 m), wn 0..3 (64 n)
    int g = lane >> 2, t = lane & 3;
    int m0 = blockIdx.y * 128;
    int n0 = blockIdx.x * 256;

    int crow = tid >> 3;            // 0..31
    int coff = (tid & 7) * 4;       // word offset

    float4 acc[4][8];
#pragma unroll
    for (int i = 0; i < 4; i++)
#pragma unroll
        for (int j = 0; j < 8; j++) acc[i][j] = make_float4(0.f, 0.f, 0.f, 0.f);

    uint32_t as_sm = smaddr(As), bs_sm = smaddr(Bs);

    auto issue = [&](int s) {
        uint32_t ab = as_sm + (s & 1) * (ATW * 4);
        uint32_t bb = bs_sm + (s & 1) * (BTW * 4);
        int k0w = s * 32;
#pragma unroll
        for (int i = 0; i < 4; i++) {
            int row = crow + i * 32;
            cp16(ab + (row * SAW + coff) * 4, Ag + (size_t)(m0 + row) * KWH + k0w + coff);
        }
#pragma unroll
        for (int i = 0; i < 8; i++) {
            int row = crow + i * 32;
            cp16(bb + (row * SAW + coff) * 4, Bg + (size_t)(n0 + row) * KWH + k0w + coff);
        }
    };

    issue(0);
    CP_COMMIT();

    const int NS = H / 64;   // 16
    for (int s = 0; s < NS; s++) {
        if (s > 0) __syncthreads();
        if (s + 1 < NS) {
            issue(s + 1);
            CP_COMMIT();
            CP_WAIT(1);
        } else {
            CP_WAIT(0);
        }
        __syncthreads();

        uint32_t ab = as_sm + (s & 1) * (ATW * 4);
        uint32_t bb = bs_sm + (s & 1) * (BTW * 4);
#pragma unroll
        for (int kw = 0; kw < 32; kw += 8) {
            uint32_t af[4][4];
#pragma unroll
            for (int im = 0; im < 4; im++)
                ldsm4(af[im], ab + ((wm * 64 + im * 16 + (lane & 15)) * SAW + kw) * 4 + (lane >> 4) * 16);
            uint32_t bq[4][4];
#pragma unroll
            for (int p = 0; p < 4; p++)
                ldsm4(bq[p], bb + ((wn * 64 + p * 16 + (lane & 15)) * SAW + kw) * 4 + (lane >> 4) * 16);
#pragma unroll
            for (int im = 0; im < 4; im++)
#pragma unroll
                for (int jn = 0; jn < 8; jn++)
                    mma_bf16(acc[im][jn], af[im], bq[jn >> 1][jn & 1], bq[jn >> 1][(jn & 1) + 2]);
        }
    }

    // epilogue
#pragma unroll
    for (int im = 0; im < 4; im++) {
        int rlo = m0 + wm * 64 + im * 16 + g;
#pragma unroll
        for (int jn = 0; jn < 8; jn++) {
            int n = n0 + wn * 64 + jn * 8 + 2 * t;
            float b0 = bias[n], b1 = bias[n + 1];
#pragma unroll
            for (int h = 0; h < 2; h++) {
                int m = h ? (rlo + 8) : rlo;
                float vx = (h ? acc[im][jn].z : acc[im][jn].x) + b0;
                float vy = (h ? acc[im][jn].w : acc[im][jn].y) + b1;
                if (MODE == 0) {
                    int c = n >> 10;
                    int rem = n & 1023;
                    int hh = rem >> 6;
                    int d = rem & 63;
                    int bb2 = m >> 11;
                    int sIdx = m & 2047;
                    float* dst = g_qkv + ((((size_t)(c * 2 + bb2) * NH + hh) * SS + sIdx) * HD + d);
                    *(float2*)dst = make_float2(vx, vy);
                } else {
                    size_t idx = (size_t)m * H + n;
                    float2 hv = *(const float2*)(resid + idx);
                    *(float2*)(outp + idx) = make_float2(vx + hv.x, vy + hv.y);
                }
            }
        }
    }
}

// ============================================================
// Flash attention (Round-5 proven): bf16 mma.sync, row-complete warp
// tiling, Vt transposed in smem; finalize -> bf16 g_ctxb.
// ============================================================
#define SQW 36
#define SKPW 68
#define SVW 68
#define QW_OFF 0
#define KPW_OFF (128 * SQW)
#define VW_OFF (KPW_OFF + 128 * SKPW)
#define ATTN_SMEM_BYTES ((VW_OFF + 64 * SVW) * 4)

__global__ __launch_bounds__(256, 1) void attn_kernel() {
    extern __shared__ uint32_t sm[];
    uint32_t* Qs = sm + QW_OFF;
    uint32_t* KP = sm + KPW_OFF;
    uint32_t* Vt = sm + VW_OFF;

    int tid = threadIdx.x;
    int lane = tid & 31;
    int warp = tid >> 5;
    int g = lane >> 2;
    int t = lane & 3;
    int bh = blockIdx.y;
    int m0 = blockIdx.x * 128;

    const float* qp = g_qkv + (size_t)(0 + bh) * (SS * HD);
    const float* kp = g_qkv + (size_t)(32 + bh) * (SS * HD);
    const float* vp = g_qkv + (size_t)(64 + bh) * (SS * HD);

    int srow = tid >> 4;
    int sc4  = (tid & 15) * 4;
#pragma unroll
    for (int i = 0; i < 8; i++) {
        int row = srow + i * 16;
        float4 v = *(const float4*)(qp + (size_t)(m0 + row) * HD + sc4);
        *(uint2*)&Qs[row * SQW + (sc4 >> 1)] = make_uint2(bf2(v.x, v.y), bf2(v.z, v.w));
    }

    int vj = tid & 63;
    int vdg = tid >> 6;

    float m0s = -1e30f, m1s = -1e30f;
    float l0 = 0.f, l1 = 0.f;
    float4 oacc[8];
#pragma unroll
    for (int jd = 0; jd < 8; jd++) oacc[jd] = make_float4(0.f, 0.f, 0.f, 0.f);

    for (int kv = 0; kv < SS; kv += 128) {
        __syncthreads();
#pragma unroll
        for (int i = 0; i < 8; i++) {
            int row = srow + i * 16;
            float4 kvec = *(const float4*)(kp + (size_t)(kv + row) * HD + sc4);
            *(uint2*)&KP[row * SKPW + (sc4 >> 1)] =
                make_uint2(bf2(kvec.x, kvec.y), bf2(kvec.z, kvec.w));
        }
        {
            const float* v0p = vp + (size_t)(kv + 2 * vj) * HD;
            const float* v1p = v0p + HD;
#pragma unroll
            for (int di = 0; di < 4; di++) {
                int d4 = vdg * 16 + di * 4;
                float4 v0 = *(const float4*)(v0p + d4);
                float4 v1 = *(const float4*)(v1p + d4);
                Vt[(d4 + 0) * SVW + vj] = bf2(v0.x, v1.x);
                Vt[(d4 + 1) * SVW + vj] = bf2(v0.y, v1.y);
                Vt[(d4 + 2) * SVW + vj] = bf2(v0.z, v1.z);
                Vt[(d4 + 3) * SVW + vj] = bf2(v0.w, v1.w);
            }
        }
        __syncthreads();

        float4 sc[16];
#pragma unroll
        for (int jn = 0; jn < 16; jn++) sc[jn] = make_float4(0.f, 0.f, 0.f, 0.f);
#pragma unroll
        for (int kw = 0; kw < 32; kw += 8) {
            uint32_t af[4];
            int r0 = warp * 16 + g;
            af[0] = Qs[r0 * SQW + kw + t];
            af[1] = Qs[(r0 + 8) * SQW + kw + t];
            af[2] = Qs[r0 * SQW + kw + t + 4];
            af[3] = Qs[(r0 + 8) * SQW + kw + t + 4];
#pragma unroll
            for (int jn = 0; jn < 16; jn++) {
                int nr = jn * 8 + g;
                mma_bf16(sc[jn], af, KP[nr * SKPW + kw + t], KP[nr * SKPW + kw + t + 4]);
            }
        }
        __syncthreads();

        {
            float rm0 = -1e30f, rm1 = -1e30f;
#pragma unroll
            for (int jn = 0; jn < 16; jn++) {
                sc[jn].x *= 0.125f; sc[jn].y *= 0.125f;
                sc[jn].z *= 0.125f; sc[jn].w *= 0.125f;
                rm0 = fmaxf(rm0, fmaxf(sc[jn].x, sc[jn].y));
                rm1 = fmaxf(rm1, fmaxf(sc[jn].z, sc[jn].w));
            }
            rm0 = fmaxf(rm0, __shfl_xor_sync(0xffffffffu, rm0, 1));
            rm0 = fmaxf(rm0, __shfl_xor_sync(0xffffffffu, rm0, 2));
            rm1 = fmaxf(rm1, __shfl_xor_sync(0xffffffffu, rm1, 1));
            rm1 = fmaxf(rm1, __shfl_xor_sync(0xffffffffu, rm1, 2));
            float nm0 = fmaxf(m0s, rm0), nm1 = fmaxf(m1s, rm1);
            float a0 = __expf(m0s - nm0), a1 = __expf(m1s - nm1);
            m0s = nm0; m1s = nm1;
            float rs0 = 0.f, rs1 = 0.f;
#pragma unroll
            for (int jn = 0; jn < 16; jn++) {
                sc[jn].x = __expf(sc[jn].x - nm0);
                sc[jn].y = __expf(sc[jn].y - nm0);
                sc[jn].z = __expf(sc[jn].z - nm1);
                sc[jn].w = __expf(sc[jn].w - nm1);
                rs0 += sc[jn].x + sc[jn].y;
                rs1 += sc[jn].z + sc[jn].w;
            }
            rs0 += __shfl_xor_sync(0xffffffffu, rs0, 1);
            rs0 += __shfl_xor_sync(0xffffffffu, rs0, 2);
            rs1 += __shfl_xor_sync(0xffffffffu, rs1, 1);
            rs1 += __shfl_xor_sync(0xffffffffu, rs1, 2);
            l0 = l0 * a0 + rs0;
            l1 = l1 * a1 + rs1;
#pragma unroll
            for (int jd = 0; jd < 8; jd++) {
                oacc[jd].x *= a0; oacc[jd].y *= a0;
                oacc[jd].z *= a1; oacc[jd].w *= a1;
            }
            int rlo = warp * 16 + g, rhi = rlo + 8;
#pragma unroll
            for (int jn = 0; jn < 16; jn++) {
                KP[rlo * SKPW + jn * 4 + t] = bf2(sc[jn].x, sc[jn].y);
                KP[rhi * SKPW + jn * 4 + t] = bf2(sc[jn].z, sc[jn].w);
            }
        }

        // no barrier: P words below are read by their writer thread
#pragma unroll
        for (int kw = 0; kw < 64; kw += 8) {
            uint32_t af[4];
            int r0 = warp * 16 + g;
            af[0] = KP[r0 * SKPW + kw + t];
            af[1] = KP[(r0 + 8) * SKPW + kw + t];
            af[2] = KP[r0 * SKPW + kw + t + 4];
            af[3] = KP[(r0 + 8) * SKPW + kw + t + 4];
#pragma unroll
            for (int jd = 0; jd < 8; jd++) {
                int nd = jd * 8 + g;
                mma_bf16(oacc[jd], af, Vt[nd * SVW + kw + t], Vt[nd * SVW + kw + t + 4]);
            }
        }
    }

    // finalize -> g_ctxb (bf16x2): ctx[t, hh*64 + d]
    int b = bh >> 4, hh = bh & 15;
    float inv0 = 1.0f / l0, inv1 = 1.0f / l1;
    size_t t0 = (size_t)(b * SS + m0 + warp * 16 + g);
    size_t t1 = t0 + 8;
#pragma unroll
    for (int jd = 0; jd < 8; jd++) {
        int w = hh * 32 + jd * 4 + t;
        g_ctxb[t0 * KWH + w] = bf2(oacc[jd].x * inv0, oacc[jd].y * inv0);
        g_ctxb[t1 * KWH + w] = bf2(oacc[jd].z * inv1, oacc[jd].w * inv1);
    }
}

// ============================================================
extern "C" void kernel_launch(void* const* d_in, const int* in_sizes, int n_in,
                              void* d_out, int out_size) {
    const float* hidden = (const float*)d_in[0];
    const float* gamma  = (const float*)d_in[1];
    const float* beta   = (const float*)d_in[2];
    const float* Wqkv   = (const float*)d_in[3];
    const float* bqkv   = (const float*)d_in[4];
    const float* Wout   = (const float*)d_in[5];
    const float* bout   = (const float*)d_in[6];
    float* out = (float*)d_out;

    tobf<<<(K3 * KWH) / 256, 256>>>(Wqkv, 0, K3 * KWH);
    tobf<<<(H * KWH) / 256, 256>>>(Wout, 1, H * KWH);
    ln_kernel<<<T, 256>>>(hidden, gamma, beta);

    cudaFuncSetAttribute(gemm_bf16<0>, cudaFuncAttributeMaxDynamicSharedMemorySize, GEMM_SMEM);
    cudaFuncSetAttribute(gemm_bf16<1>, cudaFuncAttributeMaxDynamicSharedMemorySize, GEMM_SMEM);
    cudaFuncSetAttribute(attn_kernel, cudaFuncAttributeMaxDynamicSharedMemorySize, ATTN_SMEM_BYTES);

    gemm_bf16<0><<<dim3(K3 / 256, T / 128), 256, GEMM_SMEM>>>(bqkv, nullptr, nullptr);

    attn_kernel<<<dim3(SS / 128, BB * NH), 256, ATTN_SMEM_BYTES>>>();

    gemm_bf16<1><<<dim3(H / 256, T / 128), 256, GEMM_SMEM>>>(bout, hidden, out);
}

// round 9
// speedup vs baseline: 1.2095x; 1.0425x over previous
#include <cuda_runtime.h>
#include <cuda_bf16.h>
#include <cstdint>

#define H  1024
#define NH 16
#define HD 64
#define BB 2
#define SS 2048
#define T  (BB * SS)      // 4096
#define K3 (3 * H)        // 3072
#define KWH 512           // H in bf16x2 words
#define QSCALE 0.18033688f   // 0.125 * log2(e)

// ---- scratch: referenced ONLY from device code (host arg = shadow bug!) ----
__device__ uint32_t g_xnb[(size_t)T * KWH];              // LN out bf16x2
__device__ uint32_t g_wqkv[(size_t)K3 * KWH];            // W_qkv bf16x2
__device__ uint32_t g_wout[(size_t)H * KWH];             // W_out bf16x2
__device__ uint32_t g_qb[(size_t)32 * SS * 32];          // Q bf16x2 [bh][s][d/2], pre-scaled
__device__ uint32_t g_kb[(size_t)32 * SS * 32];          // K bf16x2
__device__ uint32_t g_vb[(size_t)32 * SS * 32];          // V bf16x2
__device__ uint32_t g_ctxb[(size_t)T * KWH];             // ctx bf16x2

// ============================================================
// helpers
// ============================================================
__device__ __forceinline__ uint32_t bf2(float lo, float hi) {
    uint32_t r;
    asm("cvt.rn.bf16x2.f32 %0, %1, %2;" : "=r"(r) : "f"(hi), "f"(lo));
    return r;
}
__device__ __forceinline__ float ex2(float x) {
    float r;
    asm("ex2.approx.f32 %0, %1;" : "=f"(r) : "f"(x));
    return r;
}
__device__ __forceinline__ uint32_t prmt(uint32_t a, uint32_t b, uint32_t sel) {
    uint32_t r;
    asm("prmt.b32 %0, %1, %2, %3;" : "=r"(r) : "r"(a), "r"(b), "r"(sel));
    return r;
}
__device__ __forceinline__ void mma_bf16(float4& c, const uint32_t a[4], uint32_t b0, uint32_t b1) {
    asm volatile(
        "mma.sync.aligned.m16n8k16.row.col.f32.bf16.bf16.f32 "
        "{%0,%1,%2,%3}, {%4,%5,%6,%7}, {%8,%9}, {%0,%1,%2,%3};"
        : "+f"(c.x), "+f"(c.y), "+f"(c.z), "+f"(c.w)
        : "r"(a[0]), "r"(a[1]), "r"(a[2]), "r"(a[3]), "r"(b0), "r"(b1));
}
__device__ __forceinline__ uint32_t smaddr(const void* p) {
    return (uint32_t)__cvta_generic_to_shared(p);
}
__device__ __forceinline__ void cp16(uint32_t dst, const void* src) {
    asm volatile("cp.async.cg.shared.global [%0], [%1], 16;" :: "r"(dst), "l"(src));
}
#define CP_COMMIT() asm volatile("cp.async.commit_group;")
#define CP_WAIT(n)  asm volatile("cp.async.wait_group %0;" :: "n"(n))
__device__ __forceinline__ void ldsm4(uint32_t* r, uint32_t a) {
    asm volatile("ldmatrix.sync.aligned.m8n8.x4.shared.b16 {%0,%1,%2,%3}, [%4];"
                 : "=r"(r[0]), "=r"(r[1]), "=r"(r[2]), "=r"(r[3]) : "r"(a));
}

// ============================================================
// weight fp32 -> bf16x2
// ============================================================
__global__ __launch_bounds__(256) void tobf(const float* __restrict__ src, int which, int nwords) {
    uint32_t* dst = which ? g_wout : g_wqkv;
    int i = blockIdx.x * 256 + threadIdx.x;
    if (i < nwords) dst[i] = bf2(src[2 * i], src[2 * i + 1]);
}

// ============================================================
// LayerNorm -> bf16x2 words
// ============================================================
__global__ __launch_bounds__(256) void ln_kernel(const float* __restrict__ x,
                                                 const float* __restrict__ gamma,
                                                 const float* __restrict__ beta) {
    int row = blockIdx.x;
    int tid = threadIdx.x;
    float4 v = ((const float4*)(x + (size_t)row * H))[tid];
    float s  = v.x + v.y + v.z + v.w;
    float ss = v.x * v.x + v.y * v.y + v.z * v.z + v.w * v.w;
#pragma unroll
    for (int off = 16; off > 0; off >>= 1) {
        s  += __shfl_xor_sync(0xffffffffu, s, off);
        ss += __shfl_xor_sync(0xffffffffu, ss, off);
    }
    __shared__ float red[16];
    int warp = tid >> 5, lane = tid & 31;
    if (lane == 0) { red[warp] = s; red[8 + warp] = ss; }
    __syncthreads();
    float ts = 0.f, tss = 0.f;
#pragma unroll
    for (int w = 0; w < 8; w++) { ts += red[w]; tss += red[8 + w]; }
    float mu   = ts * (1.0f / H);
    float var  = tss * (1.0f / H) - mu * mu;
    float rstd = rsqrtf(var + 1e-5f);
    float4 g  = ((const float4*)gamma)[tid];
    float4 bt = ((const float4*)beta)[tid];
    float ox = (v.x - mu) * rstd * g.x + bt.x;
    float oy = (v.y - mu) * rstd * g.y + bt.y;
    float oz = (v.z - mu) * rstd * g.z + bt.z;
    float ow = (v.w - mu) * rstd * g.w + bt.w;
    g_xnb[(size_t)row * KWH + tid * 2 + 0] = bf2(ox, oy);
    g_xnb[(size_t)row * KWH + tid * 2 + 1] = bf2(oz, ow);
}

// ============================================================
// Big-warp-tile bf16 GEMM: CTA 128x256, BK=64, warp tile 64x64.
// MODE 0: A=g_xnb, B=g_wqkv -> bf16 g_qb (scaled) / g_kb / g_vb
// MODE 1: A=g_ctxb, B=g_wout -> fp32 out (+bias+resid)
// ============================================================
#define SAW 36
#define ATW (128 * SAW)
#define BTW (256 * SAW)
#define GEMM_SMEM ((2 * ATW + 2 * BTW) * 4)   // 110592 B

template <int MODE>
__global__ __launch_bounds__(256, 1) void gemm_bf16(const float* __restrict__ bias,
                                                    const float* __restrict__ resid,
                                                    float* __restrict__ outp) {
    extern __shared__ uint32_t smw[];
    uint32_t* As = smw;
    uint32_t* Bs = smw + 2 * ATW;
    const uint32_t* Ag = (MODE == 0) ? g_xnb : g_ctxb;
    const uint32_t* Bg = (MODE == 0) ? g_wqkv : g_wout;

    int tid = threadIdx.x;
    int lane = tid & 31;
    int warp = tid >> 5;
    int wm = warp >> 2, wn = warp & 3;
    int g = lane >> 2, t = lane & 3;
    int m0 = blockIdx.y * 128;
    int n0 = blockIdx.x * 256;

    int crow = tid >> 3;
    int coff = (tid & 7) * 4;

    float4 acc[4][8];
#pragma unroll
    for (int i = 0; i < 4; i++)
#pragma unroll
        for (int j = 0; j < 8; j++) acc[i][j] = make_float4(0.f, 0.f, 0.f, 0.f);

    uint32_t as_sm = smaddr(As), bs_sm = smaddr(Bs);

    auto issue = [&](int s) {
        uint32_t ab = as_sm + (s & 1) * (ATW * 4);
        uint32_t bb = bs_sm + (s & 1) * (BTW * 4);
        int k0w = s * 32;
#pragma unroll
        for (int i = 0; i < 4; i++) {
            int row = crow + i * 32;
            cp16(ab + (row * SAW + coff) * 4, Ag + (size_t)(m0 + row) * KWH + k0w + coff);
        }
#pragma unroll
        for (int i = 0; i < 8; i++) {
            int row = crow + i * 32;
            cp16(bb + (row * SAW + coff) * 4, Bg + (size_t)(n0 + row) * KWH + k0w + coff);
        }
    };

    issue(0);
    CP_COMMIT();

    const int NS = H / 64;
    for (int s = 0; s < NS; s++) {
        if (s > 0) __syncthreads();
        if (s + 1 < NS) {
            issue(s + 1);
            CP_COMMIT();
            CP_WAIT(1);
        } else {
            CP_WAIT(0);
        }
        __syncthreads();

        uint32_t ab = as_sm + (s & 1) * (ATW * 4);
        uint32_t bb = bs_sm + (s & 1) * (BTW * 4);
#pragma unroll
        for (int kw = 0; kw < 32; kw += 8) {
            uint32_t af[4][4];
#pragma unroll
            for (int im = 0; im < 4; im++)
                ldsm4(af[im], ab + ((wm * 64 + im * 16 + (lane & 15)) * SAW + kw) * 4 + (lane >> 4) * 16);
            uint32_t bq[4][4];
#pragma unroll
            for (int p = 0; p < 4; p++)
                ldsm4(bq[p], bb + ((wn * 64 + p * 16 + (lane & 15)) * SAW + kw) * 4 + (lane >> 4) * 16);
#pragma unroll
            for (int im = 0; im < 4; im++)
#pragma unroll
                for (int jn = 0; jn < 8; jn++)
                    mma_bf16(acc[im][jn], af[im], bq[jn >> 1][jn & 1], bq[jn >> 1][(jn & 1) + 2]);
        }
    }

    // epilogue
#pragma unroll
    for (int im = 0; im < 4; im++) {
        int rlo = m0 + wm * 64 + im * 16 + g;
#pragma unroll
        for (int jn = 0; jn < 8; jn++) {
            int n = n0 + wn * 64 + jn * 8 + 2 * t;
            float b0 = bias[n], b1 = bias[n + 1];
#pragma unroll
            for (int h = 0; h < 2; h++) {
                int m = h ? (rlo + 8) : rlo;
                float vx = (h ? acc[im][jn].z : acc[im][jn].x) + b0;
                float vy = (h ? acc[im][jn].w : acc[im][jn].y) + b1;
                if (MODE == 0) {
                    int c = n >> 10;
                    int rem = n & 1023;
                    int hh = rem >> 6;
                    int d = rem & 63;
                    int bb2 = m >> 11;
                    int sIdx = m & 2047;
                    int bh = bb2 * NH + hh;
                    size_t widx = ((size_t)bh * SS + sIdx) * 32 + (d >> 1);
                    if (c == 0)      g_qb[widx] = bf2(vx * QSCALE, vy * QSCALE);
                    else if (c == 1) g_kb[widx] = bf2(vx, vy);
                    else             g_vb[widx] = bf2(vx, vy);
                } else {
                    size_t idx = (size_t)m * H + n;
                    float2 hv = *(const float2*)(resid + idx);
                    *(float2*)(outp + idx) = make_float2(vx + hv.x, vy + hv.y);
                }
            }
        }
    }
}

// ============================================================
// Flash attention: bf16 inputs (Q pre-scaled by 0.125*log2e), ex2 softmax.
// smem words: Qs[128][36], KP[128][68] (K, then P), Vt[64][68]
// warp w owns q-rows [w*16, w*16+16) x full n/d extent.
// ============================================================
#define SQW 36
#define SKPW 68
#define SVW 68
#define QW_OFF 0
#define KPW_OFF (128 * SQW)
#define VW_OFF (KPW_OFF + 128 * SKPW)
#define ATTN_SMEM_BYTES ((VW_OFF + 64 * SVW) * 4)

__global__ __launch_bounds__(256, 1) void attn_kernel() {
    extern __shared__ uint32_t sm[];
    uint32_t* Qs = sm + QW_OFF;
    uint32_t* KP = sm + KPW_OFF;
    uint32_t* Vt = sm + VW_OFF;

    int tid = threadIdx.x;
    int lane = tid & 31;
    int warp = tid >> 5;
    int g = lane >> 2;
    int t = lane & 3;
    int bh = blockIdx.y;
    int m0 = blockIdx.x * 128;

    const uint32_t* qg = g_qb + (size_t)bh * SS * 32;
    const uint32_t* kg = g_kb + (size_t)bh * SS * 32;
    const uint32_t* vg = g_vb + (size_t)bh * SS * 32;

    // stage Q: raw copy, row = 32 words, 2 threads/row
    int qrow = tid >> 1;
    int qh   = (tid & 1) * 16;
#pragma unroll
    for (int j = 0; j < 4; j++) {
        uint4 v = *(const uint4*)(qg + (size_t)(m0 + qrow) * 32 + qh + j * 4);
        *(uint4*)&Qs[qrow * SQW + qh + j * 4] = v;
    }

    int vj = tid & 63;           // s-pair 0..63
    int vdg = tid >> 6;          // d quarter 0..3

    float m0s = -1e30f, m1s = -1e30f;
    float l0 = 0.f, l1 = 0.f;
    float4 oacc[8];
#pragma unroll
    for (int jd = 0; jd < 8; jd++) oacc[jd] = make_float4(0.f, 0.f, 0.f, 0.f);

    for (int kv = 0; kv < SS; kv += 128) {
        __syncthreads();
        // stage K: raw copy
#pragma unroll
        for (int j = 0; j < 4; j++) {
            uint4 v = *(const uint4*)(kg + (size_t)(kv + qrow) * 32 + qh + j * 4);
            *(uint4*)&KP[qrow * SKPW + qh + j * 4] = v;
        }
        // stage V transposed via PRMT: Vt[d][j] = (V[kv+2j][d], V[kv+2j+1][d])
        {
            const uint32_t* rA = vg + (size_t)(kv + 2 * vj) * 32 + vdg * 8;
            const uint32_t* rB = rA + 32;
#pragma unroll
            for (int q = 0; q < 2; q++) {
                uint4 a = *(const uint4*)(rA + q * 4);
                uint4 b = *(const uint4*)(rB + q * 4);
                int db = vdg * 16 + q * 8;
                Vt[(db + 0) * SVW + vj] = prmt(a.x, b.x, 0x5410);
                Vt[(db + 1) * SVW + vj] = prmt(a.x, b.x, 0x7632);
                Vt[(db + 2) * SVW + vj] = prmt(a.y, b.y, 0x5410);
                Vt[(db + 3) * SVW + vj] = prmt(a.y, b.y, 0x7632);
                Vt[(db + 4) * SVW + vj] = prmt(a.z, b.z, 0x5410);
                Vt[(db + 5) * SVW + vj] = prmt(a.z, b.z, 0x7632);
                Vt[(db + 6) * SVW + vj] = prmt(a.w, b.w, 0x5410);
                Vt[(db + 7) * SVW + vj] = prmt(a.w, b.w, 0x7632);
            }
        }
        __syncthreads();

        // S = Q K^T : warp tile m16 x n128, k=64 (4 k16 steps)
        float4 sc[16];
#pragma unroll
        for (int jn = 0; jn < 16; jn++) sc[jn] = make_float4(0.f, 0.f, 0.f, 0.f);
#pragma unroll
        for (int kw = 0; kw < 32; kw += 8) {
            uint32_t af[4];
            int r0 = warp * 16 + g;
            af[0] = Qs[r0 * SQW + kw + t];
            af[1] = Qs[(r0 + 8) * SQW + kw + t];
            af[2] = Qs[r0 * SQW + kw + t + 4];
            af[3] = Qs[(r0 + 8) * SQW + kw + t + 4];
#pragma unroll
            for (int jn = 0; jn < 16; jn++) {
                int nr = jn * 8 + g;
                mma_bf16(sc[jn], af, KP[nr * SKPW + kw + t], KP[nr * SKPW + kw + t + 4]);
            }
        }
        __syncthreads();

        // warp-local online softmax (log2 domain, ex2)
        {
            float rm0 = -1e30f, rm1 = -1e30f;
#pragma unroll
            for (int jn = 0; jn < 16; jn++) {
                rm0 = fmaxf(rm0, fmaxf(sc[jn].x, sc[jn].y));
                rm1 = fmaxf(rm1, fmaxf(sc[jn].z, sc[jn].w));
            }
            rm0 = fmaxf(rm0, __shfl_xor_sync(0xffffffffu, rm0, 1));
            rm0 = fmaxf(rm0, __shfl_xor_sync(0xffffffffu, rm0, 2));
            rm1 = fmaxf(rm1, __shfl_xor_sync(0xffffffffu, rm1, 1));
            rm1 = fmaxf(rm1, __shfl_xor_sync(0xffffffffu, rm1, 2));
            float nm0 = fmaxf(m0s, rm0), nm1 = fmaxf(m1s, rm1);
            float a0 = ex2(m0s - nm0), a1 = ex2(m1s - nm1);
            m0s = nm0; m1s = nm1;
            float rs0 = 0.f, rs1 = 0.f;
#pragma unroll
            for (int jn = 0; jn < 16; jn++) {
                sc[jn].x = ex2(sc[jn].x - nm0);
                sc[jn].y = ex2(sc[jn].y - nm0);
                sc[jn].z = ex2(sc[jn].z - nm1);
                sc[jn].w = ex2(sc[jn].w - nm1);
                rs0 += sc[jn].x + sc[jn].y;
                rs1 += sc[jn].z + sc[jn].w;
            }
            rs0 += __shfl_xor_sync(0xffffffffu, rs0, 1);
            rs0 += __shfl_xor_sync(0xffffffffu, rs0, 2);
            rs1 += __shfl_xor_sync(0xffffffffu, rs1, 1);
            rs1 += __shfl_xor_sync(0xffffffffu, rs1, 2);
            l0 = l0 * a0 + rs0;
            l1 = l1 * a1 + rs1;
#pragma unroll
            for (int jd = 0; jd < 8; jd++) {
                oacc[jd].x *= a0; oacc[jd].y *= a0;
                oacc[jd].z *= a1; oacc[jd].w *= a1;
            }
            int rlo = warp * 16 + g, rhi = rlo + 8;
#pragma unroll
            for (int jn = 0; jn < 16; jn++) {
                KP[rlo * SKPW + jn * 4 + t] = bf2(sc[jn].x, sc[jn].y);
                KP[rhi * SKPW + jn * 4 + t] = bf2(sc[jn].z, sc[jn].w);
            }
        }

        // no barrier: P words below are read by their writer thread
#pragma unroll
        for (int kw = 0; kw < 64; kw += 8) {
            uint32_t af[4];
            int r0 = warp * 16 + g;
            af[0] = KP[r0 * SKPW + kw + t];
            af[1] = KP[(r0 + 8) * SKPW + kw + t];
            af[2] = KP[r0 * SKPW + kw + t + 4];
            af[3] = KP[(r0 + 8) * SKPW + kw + t + 4];
#pragma unroll
            for (int jd = 0; jd < 8; jd++) {
                int nd = jd * 8 + g;
                mma_bf16(oacc[jd], af, Vt[nd * SVW + kw + t], Vt[nd * SVW + kw + t + 4]);
            }
        }
    }

    // finalize -> g_ctxb (bf16x2): ctx[t, hh*64 + d]
    int b = bh >> 4, hh = bh & 15;
    float inv0 = 1.0f / l0, inv1 = 1.0f / l1;
    size_t t0 = (size_t)(b * SS + m0 + warp * 16 + g);
    size_t t1 = t0 + 8;
#pragma unroll
    for (int jd = 0; jd < 8; jd++) {
        int w = hh * 32 + jd * 4 + t;
        g_ctxb[t0 * KWH + w] = bf2(oacc[jd].x * inv0, oacc[jd].y * inv0);
        g_ctxb[t1 * KWH + w] = bf2(oacc[jd].z * inv1, oacc[jd].w * inv1);
    }
}

// ============================================================
extern "C" void kernel_launch(void* const* d_in, const int* in_sizes, int n_in,
                              void* d_out, int out_size) {
    const float* hidden = (const float*)d_in[0];
    const float* gamma  = (const float*)d_in[1];
    const float* beta   = (const float*)d_in[2];
    const float* Wqkv   = (const float*)d_in[3];
    const float* bqkv   = (const float*)d_in[4];
    const float* Wout   = (const float*)d_in[5];
    const float* bout   = (const float*)d_in[6];
    float* out = (float*)d_out;

    tobf<<<(K3 * KWH) / 256, 256>>>(Wqkv, 0, K3 * KWH);
    tobf<<<(H * KWH) / 256, 256>>>(Wout, 1, H * KWH);
    ln_kernel<<<T, 256>>>(hidden, gamma, beta);

    cudaFuncSetAttribute(gemm_bf16<0>, cudaFuncAttributeMaxDynamicSharedMemorySize, GEMM_SMEM);
    cudaFuncSetAttribute(gemm_bf16<1>, cudaFuncAttributeMaxDynamicSharedMemorySize, GEMM_SMEM);
    cudaFuncSetAttribute(attn_kernel, cudaFuncAttributeMaxDynamicSharedMemorySize, ATTN_SMEM_BYTES);

    gemm_bf16<0><<<dim3(K3 / 256, T / 128), 256, GEMM_SMEM>>>(bqkv, nullptr, nullptr);

    attn_kernel<<<dim3(SS / 128, BB * NH), 256, ATTN_SMEM_BYTES>>>();

    gemm_bf16<1><<<dim3(H / 256, T / 128), 256, GEMM_SMEM>>>(bout, hidden, out);
}

// round 10
// speedup vs baseline: 1.2562x; 1.0385x over previous
#include <cuda_runtime.h>
#include <cuda_bf16.h>
#include <cstdint>

#define H  1024
#define NH 16
#define HD 64
#define BB 2
#define SS 2048
#define T  (BB * SS)      // 4096
#define K3 (3 * H)        // 3072
#define KWH 512           // H in bf16x2 words
#define QSCALE 0.18033688f   // 0.125 * log2(e)

// ---- scratch: referenced ONLY from device code (host arg = shadow bug!) ----
__device__ uint32_t g_xnb[(size_t)T * KWH];              // LN out bf16x2
__device__ uint32_t g_wqkv[(size_t)K3 * KWH];            // W_qkv bf16x2
__device__ uint32_t g_wout[(size_t)H * KWH];             // W_out bf16x2
__device__ uint32_t g_qb[(size_t)32 * SS * 32];          // Q bf16x2 [bh][s][d/2], pre-scaled
__device__ uint32_t g_kb[(size_t)32 * SS * 32];          // K bf16x2
__device__ uint32_t g_vb[(size_t)32 * SS * 32];          // V bf16x2
__device__ uint32_t g_ctxb[(size_t)T * KWH];             // ctx bf16x2

// ============================================================
// helpers
// ============================================================
__device__ __forceinline__ uint32_t bf2(float lo, float hi) {
    uint32_t r;
    asm("cvt.rn.bf16x2.f32 %0, %1, %2;" : "=r"(r) : "f"(hi), "f"(lo));
    return r;
}
__device__ __forceinline__ float ex2(float x) {
    float r;
    asm("ex2.approx.f32 %0, %1;" : "=f"(r) : "f"(x));
    return r;
}
__device__ __forceinline__ uint32_t prmt(uint32_t a, uint32_t b, uint32_t sel) {
    uint32_t r;
    asm("prmt.b32 %0, %1, %2, %3;" : "=r"(r) : "r"(a), "r"(b), "r"(sel));
    return r;
}
__device__ __forceinline__ void mma_bf16(float4& c, const uint32_t a[4], uint32_t b0, uint32_t b1) {
    asm volatile(
        "mma.sync.aligned.m16n8k16.row.col.f32.bf16.bf16.f32 "
        "{%0,%1,%2,%3}, {%4,%5,%6,%7}, {%8,%9}, {%0,%1,%2,%3};"
        : "+f"(c.x), "+f"(c.y), "+f"(c.z), "+f"(c.w)
        : "r"(a[0]), "r"(a[1]), "r"(a[2]), "r"(a[3]), "r"(b0), "r"(b1));
}
__device__ __forceinline__ uint32_t smaddr(const void* p) {
    return (uint32_t)__cvta_generic_to_shared(p);
}
__device__ __forceinline__ void cp16(uint32_t dst, const void* src) {
    asm volatile("cp.async.cg.shared.global [%0], [%1], 16;" :: "r"(dst), "l"(src));
}
#define CP_COMMIT() asm volatile("cp.async.commit_group;")
#define CP_WAIT(n)  asm volatile("cp.async.wait_group %0;" :: "n"(n))
__device__ __forceinline__ void ldsm4(uint32_t* r, uint32_t a) {
    asm volatile("ldmatrix.sync.aligned.m8n8.x4.shared.b16 {%0,%1,%2,%3}, [%4];"
                 : "=r"(r[0]), "=r"(r[1]), "=r"(r[2]), "=r"(r[3]) : "r"(a));
}

// ============================================================
// weight fp32 -> bf16x2
// ============================================================
__global__ __launch_bounds__(256) void tobf(const float* __restrict__ src, int which, int nwords) {
    uint32_t* dst = which ? g_wout : g_wqkv;
    int i = blockIdx.x * 256 + threadIdx.x;
    if (i < nwords) dst[i] = bf2(src[2 * i], src[2 * i + 1]);
}

// ============================================================
// LayerNorm -> bf16x2 words
// ============================================================
__global__ __launch_bounds__(256) void ln_kernel(const float* __restrict__ x,
                                                 const float* __restrict__ gamma,
                                                 const float* __restrict__ beta) {
    int row = blockIdx.x;
    int tid = threadIdx.x;
    float4 v = ((const float4*)(x + (size_t)row * H))[tid];
    float s  = v.x + v.y + v.z + v.w;
    float ss = v.x * v.x + v.y * v.y + v.z * v.z + v.w * v.w;
#pragma unroll
    for (int off = 16; off > 0; off >>= 1) {
        s  += __shfl_xor_sync(0xffffffffu, s, off);
        ss += __shfl_xor_sync(0xffffffffu, ss, off);
    }
    __shared__ float red[16];
    int warp = tid >> 5, lane = tid & 31;
    if (lane == 0) { red[warp] = s; red[8 + warp] = ss; }
    __syncthreads();
    float ts = 0.f, tss = 0.f;
#pragma unroll
    for (int w = 0; w < 8; w++) { ts += red[w]; tss += red[8 + w]; }
    float mu   = ts * (1.0f / H);
    float var  = tss * (1.0f / H) - mu * mu;
    float rstd = rsqrtf(var + 1e-5f);
    float4 g  = ((const float4*)gamma)[tid];
    float4 bt = ((const float4*)beta)[tid];
    float ox = (v.x - mu) * rstd * g.x + bt.x;
    float oy = (v.y - mu) * rstd * g.y + bt.y;
    float oz = (v.z - mu) * rstd * g.z + bt.z;
    float ow = (v.w - mu) * rstd * g.w + bt.w;
    g_xnb[(size_t)row * KWH + tid * 2 + 0] = bf2(ox, oy);
    g_xnb[(size_t)row * KWH + tid * 2 + 1] = bf2(oz, ow);
}

// ============================================================
// Big-warp-tile bf16 GEMM (unchanged from R8/R9): CTA 128x256, BK=64.
// MODE 0: A=g_xnb, B=g_wqkv -> bf16 g_qb (scaled) / g_kb / g_vb
// MODE 1: A=g_ctxb, B=g_wout -> fp32 out (+bias+resid)
// ============================================================
#define SAW 36
#define ATW (128 * SAW)
#define BTW (256 * SAW)
#define GEMM_SMEM ((2 * ATW + 2 * BTW) * 4)   // 110592 B

template <int MODE>
__global__ __launch_bounds__(256, 1) void gemm_bf16(const float* __restrict__ bias,
                                                    const float* __restrict__ resid,
                                                    float* __restrict__ outp) {
    extern __shared__ uint32_t smw[];
    uint32_t* As = smw;
    uint32_t* Bs = smw + 2 * ATW;
    const uint32_t* Ag = (MODE == 0) ? g_xnb : g_ctxb;
    const uint32_t* Bg = (MODE == 0) ? g_wqkv : g_wout;

    int tid = threadIdx.x;
    int lane = tid & 31;
    int warp = tid >> 5;
    int wm = warp >> 2, wn = warp & 3;
    int g = lane >> 2, t = lane & 3;
    int m0 = blockIdx.y * 128;
    int n0 = blockIdx.x * 256;

    int crow = tid >> 3;
    int coff = (tid & 7) * 4;

    float4 acc[4][8];
#pragma unroll
    for (int i = 0; i < 4; i++)
#pragma unroll
        for (int j = 0; j < 8; j++) acc[i][j] = make_float4(0.f, 0.f, 0.f, 0.f);

    uint32_t as_sm = smaddr(As), bs_sm = smaddr(Bs);

    auto issue = [&](int s) {
        uint32_t ab = as_sm + (s & 1) * (ATW * 4);
        uint32_t bb = bs_sm + (s & 1) * (BTW * 4);
        int k0w = s * 32;
#pragma unroll
        for (int i = 0; i < 4; i++) {
            int row = crow + i * 32;
            cp16(ab + (row * SAW + coff) * 4, Ag + (size_t)(m0 + row) * KWH + k0w + coff);
        }
#pragma unroll
        for (int i = 0; i < 8; i++) {
            int row = crow + i * 32;
            cp16(bb + (row * SAW + coff) * 4, Bg + (size_t)(n0 + row) * KWH + k0w + coff);
        }
    };

    issue(0);
    CP_COMMIT();

    const int NS = H / 64;
    for (int s = 0; s < NS; s++) {
        if (s > 0) __syncthreads();
        if (s + 1 < NS) {
            issue(s + 1);
            CP_COMMIT();
            CP_WAIT(1);
        } else {
            CP_WAIT(0);
        }
        __syncthreads();

        uint32_t ab = as_sm + (s & 1) * (ATW * 4);
        uint32_t bb = bs_sm + (s & 1) * (BTW * 4);
#pragma unroll
        for (int kw = 0; kw < 32; kw += 8) {
            uint32_t af[4][4];
#pragma unroll
            for (int im = 0; im < 4; im++)
                ldsm4(af[im], ab + ((wm * 64 + im * 16 + (lane & 15)) * SAW + kw) * 4 + (lane >> 4) * 16);
            uint32_t bq[4][4];
#pragma unroll
            for (int p = 0; p < 4; p++)
                ldsm4(bq[p], bb + ((wn * 64 + p * 16 + (lane & 15)) * SAW + kw) * 4 + (lane >> 4) * 16);
#pragma unroll
            for (int im = 0; im < 4; im++)
#pragma unroll
                for (int jn = 0; jn < 8; jn++)
                    mma_bf16(acc[im][jn], af[im], bq[jn >> 1][jn & 1], bq[jn >> 1][(jn & 1) + 2]);
        }
    }

    // epilogue
#pragma unroll
    for (int im = 0; im < 4; im++) {
        int rlo = m0 + wm * 64 + im * 16 + g;
#pragma unroll
        for (int jn = 0; jn < 8; jn++) {
            int n = n0 + wn * 64 + jn * 8 + 2 * t;
            float b0 = bias[n], b1 = bias[n + 1];
#pragma unroll
            for (int h = 0; h < 2; h++) {
                int m = h ? (rlo + 8) : rlo;
                float vx = (h ? acc[im][jn].z : acc[im][jn].x) + b0;
                float vy = (h ? acc[im][jn].w : acc[im][jn].y) + b1;
                if (MODE == 0) {
                    int c = n >> 10;
                    int rem = n & 1023;
                    int hh = rem >> 6;
                    int d = rem & 63;
                    int bb2 = m >> 11;
                    int sIdx = m & 2047;
                    int bh = bb2 * NH + hh;
                    size_t widx = ((size_t)bh * SS + sIdx) * 32 + (d >> 1);
                    if (c == 0)      g_qb[widx] = bf2(vx * QSCALE, vy * QSCALE);
                    else if (c == 1) g_kb[widx] = bf2(vx, vy);
                    else             g_vb[widx] = bf2(vx, vy);
                } else {
                    size_t idx = (size_t)m * H + n;
                    float2 hv = *(const float2*)(resid + idx);
                    *(float2*)(outp + idx) = make_float2(vx + hv.x, vy + hv.y);
                }
            }
        }
    }
}

// ============================================================
// Flash attention: ldmatrix fragments, register-resident P, ex2 softmax.
// smem words: Qs[128][36], Ks[128][36], Vt[64][68]
// warp w owns q-rows [w*16, w*16+16) x full n/d extent.
// ============================================================
#define SQW 36
#define SKW 36
#define SVW 68
#define QW_OFF 0
#define KW_OFF (128 * SQW)
#define VW_OFF (KW_OFF + 128 * SKW)
#define ATTN_SMEM_BYTES ((VW_OFF + 64 * SVW) * 4)   // 54272 B

__global__ __launch_bounds__(256, 1) void attn_kernel() {
    extern __shared__ uint32_t sm[];
    uint32_t* Qs = sm + QW_OFF;
    uint32_t* Ks = sm + KW_OFF;
    uint32_t* Vt = sm + VW_OFF;

    int tid = threadIdx.x;
    int lane = tid & 31;
    int warp = tid >> 5;
    int g = lane >> 2;
    int t = lane & 3;
    int bh = blockIdx.y;
    int m0 = blockIdx.x * 128;

    const uint32_t* qg = g_qb + (size_t)bh * SS * 32;
    const uint32_t* kg = g_kb + (size_t)bh * SS * 32;
    const uint32_t* vg = g_vb + (size_t)bh * SS * 32;

    uint32_t qs_sm = smaddr(Qs), ks_sm = smaddr(Ks), vt_sm = smaddr(Vt);

    // stage Q: raw copy, 2 threads/row
    int qrow = tid >> 1;
    int qh   = (tid & 1) * 16;
#pragma unroll
    for (int j = 0; j < 4; j++) {
        uint4 v = *(const uint4*)(qg + (size_t)(m0 + qrow) * 32 + qh + j * 4);
        *(uint4*)&Qs[qrow * SQW + qh + j * 4] = v;
    }

    int vj = tid & 63;           // s-pair 0..63
    int vdg = tid >> 6;          // d quarter 0..3

    // hoisted ldmatrix base addresses (per-thread row lane&15, col-half lane>>4)
    uint32_t lrow = (lane & 15);
    uint32_t lhalf = (lane >> 4) * 16;
    uint32_t q_base = qs_sm + ((warp * 16 + lrow) * SQW) * 4 + lhalf;
    uint32_t k_base = ks_sm + (lrow * SKW) * 4 + lhalf;
    uint32_t v_base = vt_sm + (lrow * SVW) * 4 + lhalf;

    uint32_t af_q[4][4];
    float m0s = -1e30f, m1s = -1e30f;
    float l0 = 0.f, l1 = 0.f;
    float4 oacc[8];
#pragma unroll
    for (int jd = 0; jd < 8; jd++) oacc[jd] = make_float4(0.f, 0.f, 0.f, 0.f);

    for (int kv = 0; kv < SS; kv += 128) {
        __syncthreads();   // prev iter QK/PV reads of Ks/Vt done (Q staged, iter 0)
        // stage K: raw copy into stride-36 rows
#pragma unroll
        for (int j = 0; j < 4; j++) {
            uint4 v = *(const uint4*)(kg + (size_t)(kv + qrow) * 32 + qh + j * 4);
            *(uint4*)&Ks[qrow * SKW + qh + j * 4] = v;
        }
        // stage V transposed via PRMT: Vt[d][j] = (V[kv+2j][d], V[kv+2j+1][d])
        {
            const uint32_t* rA = vg + (size_t)(kv + 2 * vj) * 32 + vdg * 8;
            const uint32_t* rB = rA + 32;
#pragma unroll
            for (int q = 0; q < 2; q++) {
                uint4 a = *(const uint4*)(rA + q * 4);
                uint4 b = *(const uint4*)(rB + q * 4);
                int db = vdg * 16 + q * 8;
                Vt[(db + 0) * SVW + vj] = prmt(a.x, b.x, 0x5410);
                Vt[(db + 1) * SVW + vj] = prmt(a.x, b.x, 0x7632);
                Vt[(db + 2) * SVW + vj] = prmt(a.y, b.y, 0x5410);
                Vt[(db + 3) * SVW + vj] = prmt(a.y, b.y, 0x7632);
                Vt[(db + 4) * SVW + vj] = prmt(a.z, b.z, 0x5410);
                Vt[(db + 5) * SVW + vj] = prmt(a.z, b.z, 0x7632);
                Vt[(db + 6) * SVW + vj] = prmt(a.w, b.w, 0x5410);
                Vt[(db + 7) * SVW + vj] = prmt(a.w, b.w, 0x7632);
            }
        }
        __syncthreads();

        if (kv == 0) {
#pragma unroll
            for (int ks = 0; ks < 4; ks++)
                ldsm4(af_q[ks], q_base + ks * 32);   // ks*8 words * 4B
        }

        // S = Q K^T : warp tile m16 x n128, k=64 (4 k16 steps), ldmatrix B
        float4 sc[16];
#pragma unroll
        for (int jn = 0; jn < 16; jn++) sc[jn] = make_float4(0.f, 0.f, 0.f, 0.f);
#pragma unroll
        for (int ks = 0; ks < 4; ks++) {
            uint32_t bq[8][4];
#pragma unroll
            for (int p = 0; p < 8; p++)
                ldsm4(bq[p], k_base + (p * 16 * SKW + ks * 8) * 4);
#pragma unroll
            for (int p = 0; p < 8; p++) {
                mma_bf16(sc[2 * p + 0], af_q[ks], bq[p][0], bq[p][2]);
                mma_bf16(sc[2 * p + 1], af_q[ks], bq[p][1], bq[p][3]);
            }
        }

        // warp-local online softmax (log2 domain, ex2); Q pre-scaled
        float rm0 = -1e30f, rm1 = -1e30f;
#pragma unroll
        for (int jn = 0; jn < 16; jn++) {
            rm0 = fmaxf(rm0, fmaxf(sc[jn].x, sc[jn].y));
            rm1 = fmaxf(rm1, fmaxf(sc[jn].z, sc[jn].w));
        }
        rm0 = fmaxf(rm0, __shfl_xor_sync(0xffffffffu, rm0, 1));
        rm0 = fmaxf(rm0, __shfl_xor_sync(0xffffffffu, rm0, 2));
        rm1 = fmaxf(rm1, __shfl_xor_sync(0xffffffffu, rm1, 1));
        rm1 = fmaxf(rm1, __shfl_xor_sync(0xffffffffu, rm1, 2));
        float nm0 = fmaxf(m0s, rm0), nm1 = fmaxf(m1s, rm1);
        float a0 = ex2(m0s - nm0), a1 = ex2(m1s - nm1);
        m0s = nm0; m1s = nm1;
        float rs0 = 0.f, rs1 = 0.f;
#pragma unroll
        for (int jn = 0; jn < 16; jn++) {
            sc[jn].x = ex2(sc[jn].x - nm0);
            sc[jn].y = ex2(sc[jn].y - nm0);
            sc[jn].z = ex2(sc[jn].z - nm1);
            sc[jn].w = ex2(sc[jn].w - nm1);
            rs0 += sc[jn].x + sc[jn].y;
            rs1 += sc[jn].z + sc[jn].w;
        }
        rs0 += __shfl_xor_sync(0xffffffffu, rs0, 1);
        rs0 += __shfl_xor_sync(0xffffffffu, rs0, 2);
        rs1 += __shfl_xor_sync(0xffffffffu, rs1, 1);
        rs1 += __shfl_xor_sync(0xffffffffu, rs1, 2);
        l0 = l0 * a0 + rs0;
        l1 = l1 * a1 + rs1;
#pragma unroll
        for (int jd = 0; jd < 8; jd++) {
            oacc[jd].x *= a0; oacc[jd].y *= a0;
            oacc[jd].z *= a1; oacc[jd].w *= a1;
        }

        // O += P V : P in registers (QK C-frag layout == PV A-frag layout)
#pragma unroll
        for (int ks = 0; ks < 8; ks++) {
            uint32_t ap[4];
            ap[0] = bf2(sc[2 * ks].x, sc[2 * ks].y);
            ap[1] = bf2(sc[2 * ks].z, sc[2 * ks].w);
            ap[2] = bf2(sc[2 * ks + 1].x, sc[2 * ks + 1].y);
            ap[3] = bf2(sc[2 * ks + 1].z, sc[2 * ks + 1].w);
            uint32_t bqv[4][4];
#pragma unroll
            for (int p = 0; p < 4; p++)
                ldsm4(bqv[p], v_base + (p * 16 * SVW + ks * 8) * 4);
#pragma unroll
            for (int p = 0; p < 4; p++) {
                mma_bf16(oacc[2 * p + 0], ap, bqv[p][0], bqv[p][2]);
                mma_bf16(oacc[2 * p + 1], ap, bqv[p][1], bqv[p][3]);
            }
        }
    }

    // finalize -> g_ctxb (bf16x2): ctx[t, hh*64 + d]
    int b = bh >> 4, hh = bh & 15;
    float inv0 = 1.0f / l0, inv1 = 1.0f / l1;
    size_t t0 = (size_t)(b * SS + m0 + warp * 16 + g);
    size_t t1 = t0 + 8;
#pragma unroll
    for (int jd = 0; jd < 8; jd++) {
        int w = hh * 32 + jd * 4 + t;
        g_ctxb[t0 * KWH + w] = bf2(oacc[jd].x * inv0, oacc[jd].y * inv0);
        g_ctxb[t1 * KWH + w] = bf2(oacc[jd].z * inv1, oacc[jd].w * inv1);
    }
}

// ============================================================
extern "C" void kernel_launch(void* const* d_in, const int* in_sizes, int n_in,
                              void* d_out, int out_size) {
    const float* hidden = (const float*)d_in[0];
    const float* gamma  = (const float*)d_in[1];
    const float* beta   = (const float*)d_in[2];
    const float* Wqkv   = (const float*)d_in[3];
    const float* bqkv   = (const float*)d_in[4];
    const float* Wout   = (const float*)d_in[5];
    const float* bout   = (const float*)d_in[6];
    float* out = (float*)d_out;

    tobf<<<(K3 * KWH) / 256, 256>>>(Wqkv, 0, K3 * KWH);
    tobf<<<(H * KWH) / 256, 256>>>(Wout, 1, H * KWH);
    ln_kernel<<<T, 256>>>(hidden, gamma, beta);

    cudaFuncSetAttribute(gemm_bf16<0>, cudaFuncAttributeMaxDynamicSharedMemorySize, GEMM_SMEM);
    cudaFuncSetAttribute(gemm_bf16<1>, cudaFuncAttributeMaxDynamicSharedMemorySize, GEMM_SMEM);
    cudaFuncSetAttribute(attn_kernel, cudaFuncAttributeMaxDynamicSharedMemorySize, ATTN_SMEM_BYTES);

    gemm_bf16<0><<<dim3(K3 / 256, T / 128), 256, GEMM_SMEM>>>(bqkv, nullptr, nullptr);

    attn_kernel<<<dim3(SS / 128, BB * NH), 256, ATTN_SMEM_BYTES>>>();

    gemm_bf16<1><<<dim3(H / 256, T / 128), 256, GEMM_SMEM>>>(bout, hidden, out);
}

// round 11
// speedup vs baseline: 1.4177x; 1.1286x over previous
#include <cuda_runtime.h>
#include <cuda_bf16.h>
#include <cstdint>

#define H  1024
#define NH 16
#define HD 64
#define BB 2
#define SS 2048
#define T  (BB * SS)      // 4096
#define K3 (3 * H)        // 3072
#define KWH 512           // H in bf16x2 words
#define QSCALE 0.18033688f   // 0.125 * log2(e)

// ---- scratch: referenced ONLY from device code (host arg = shadow bug!) ----
__device__ uint32_t g_xnb[(size_t)T * KWH];              // LN out bf16x2
__device__ uint32_t g_wqkv[(size_t)K3 * KWH];            // W_qkv bf16x2
__device__ uint32_t g_wout[(size_t)H * KWH];             // W_out bf16x2
__device__ uint32_t g_qb[(size_t)32 * SS * 32];          // Q bf16x2 [bh][s][d/2], pre-scaled
__device__ uint32_t g_kb[(size_t)32 * SS * 32];          // K bf16x2
__device__ uint32_t g_vb[(size_t)32 * SS * 32];          // V bf16x2
__device__ uint32_t g_ctxb[(size_t)T * KWH];             // ctx bf16x2

// ============================================================
// helpers
// ============================================================
__device__ __forceinline__ uint32_t bf2(float lo, float hi) {
    uint32_t r;
    asm("cvt.rn.bf16x2.f32 %0, %1, %2;" : "=r"(r) : "f"(hi), "f"(lo));
    return r;
}
__device__ __forceinline__ float ex2(float x) {
    float r;
    asm("ex2.approx.f32 %0, %1;" : "=f"(r) : "f"(x));
    return r;
}
__device__ __forceinline__ void mma_bf16(float4& c, const uint32_t a[4], uint32_t b0, uint32_t b1) {
    asm volatile(
        "mma.sync.aligned.m16n8k16.row.col.f32.bf16.bf16.f32 "
        "{%0,%1,%2,%3}, {%4,%5,%6,%7}, {%8,%9}, {%0,%1,%2,%3};"
        : "+f"(c.x), "+f"(c.y), "+f"(c.z), "+f"(c.w)
        : "r"(a[0]), "r"(a[1]), "r"(a[2]), "r"(a[3]), "r"(b0), "r"(b1));
}
__device__ __forceinline__ uint32_t smaddr(const void* p) {
    return (uint32_t)__cvta_generic_to_shared(p);
}
__device__ __forceinline__ void cp16(uint32_t dst, const void* src) {
    asm volatile("cp.async.cg.shared.global [%0], [%1], 16;" :: "r"(dst), "l"(src));
}
#define CP_COMMIT() asm volatile("cp.async.commit_group;")
#define CP_WAIT(n)  asm volatile("cp.async.wait_group %0;" :: "n"(n))
__device__ __forceinline__ void ldsm4(uint32_t* r, uint32_t a) {
    asm volatile("ldmatrix.sync.aligned.m8n8.x4.shared.b16 {%0,%1,%2,%3}, [%4];"
                 : "=r"(r[0]), "=r"(r[1]), "=r"(r[2]), "=r"(r[3]) : "r"(a));
}
__device__ __forceinline__ void ldsm4t(uint32_t* r, uint32_t a) {
    asm volatile("ldmatrix.sync.aligned.m8n8.x4.trans.shared.b16 {%0,%1,%2,%3}, [%4];"
                 : "=r"(r[0]), "=r"(r[1]), "=r"(r[2]), "=r"(r[3]) : "r"(a));
}

// ============================================================
// weight fp32 -> bf16x2
// ============================================================
__global__ __launch_bounds__(256) void tobf(const float* __restrict__ src, int which, int nwords) {
    uint32_t* dst = which ? g_wout : g_wqkv;
    int i = blockIdx.x * 256 + threadIdx.x;
    if (i < nwords) dst[i] = bf2(src[2 * i], src[2 * i + 1]);
}

// ============================================================
// LayerNorm -> bf16x2 words
// ============================================================
__global__ __launch_bounds__(256) void ln_kernel(const float* __restrict__ x,
                                                 const float* __restrict__ gamma,
                                                 const float* __restrict__ beta) {
    int row = blockIdx.x;
    int tid = threadIdx.x;
    float4 v = ((const float4*)(x + (size_t)row * H))[tid];
    float s  = v.x + v.y + v.z + v.w;
    float ss = v.x * v.x + v.y * v.y + v.z * v.z + v.w * v.w;
#pragma unroll
    for (int off = 16; off > 0; off >>= 1) {
        s  += __shfl_xor_sync(0xffffffffu, s, off);
        ss += __shfl_xor_sync(0xffffffffu, ss, off);
    }
    __shared__ float red[16];
    int warp = tid >> 5, lane = tid & 31;
    if (lane == 0) { red[warp] = s; red[8 + warp] = ss; }
    __syncthreads();
    float ts = 0.f, tss = 0.f;
#pragma unroll
    for (int w = 0; w < 8; w++) { ts += red[w]; tss += red[8 + w]; }
    float mu   = ts * (1.0f / H);
    float var  = tss * (1.0f / H) - mu * mu;
    float rstd = rsqrtf(var + 1e-5f);
    float4 g  = ((const float4*)gamma)[tid];
    float4 bt = ((const float4*)beta)[tid];
    float ox = (v.x - mu) * rstd * g.x + bt.x;
    float oy = (v.y - mu) * rstd * g.y + bt.y;
    float oz = (v.z - mu) * rstd * g.z + bt.z;
    float ow = (v.w - mu) * rstd * g.w + bt.w;
    g_xnb[(size_t)row * KWH + tid * 2 + 0] = bf2(ox, oy);
    g_xnb[(size_t)row * KWH + tid * 2 + 1] = bf2(oz, ow);
}

// ============================================================
// Big-warp-tile bf16 GEMM (unchanged): CTA 128x256, BK=64.
// MODE 0: A=g_xnb, B=g_wqkv -> bf16 g_qb (scaled) / g_kb / g_vb
// MODE 1: A=g_ctxb, B=g_wout -> fp32 out (+bias+resid)
// ============================================================
#define SAW 36
#define ATW (128 * SAW)
#define BTW (256 * SAW)
#define GEMM_SMEM ((2 * ATW + 2 * BTW) * 4)   // 110592 B

template <int MODE>
__global__ __launch_bounds__(256, 1) void gemm_bf16(const float* __restrict__ bias,
                                                    const float* __restrict__ resid,
                                                    float* __restrict__ outp) {
    extern __shared__ uint32_t smw[];
    uint32_t* As = smw;
    uint32_t* Bs = smw + 2 * ATW;
    const uint32_t* Ag = (MODE == 0) ? g_xnb : g_ctxb;
    const uint32_t* Bg = (MODE == 0) ? g_wqkv : g_wout;

    int tid = threadIdx.x;
    int lane = tid & 31;
    int warp = tid >> 5;
    int wm = warp >> 2, wn = warp & 3;
    int g = lane >> 2, t = lane & 3;
    int m0 = blockIdx.y * 128;
    int n0 = blockIdx.x * 256;

    int crow = tid >> 3;
    int coff = (tid & 7) * 4;

    float4 acc[4][8];
#pragma unroll
    for (int i = 0; i < 4; i++)
#pragma unroll
        for (int j = 0; j < 8; j++) acc[i][j] = make_float4(0.f, 0.f, 0.f, 0.f);

    uint32_t as_sm = smaddr(As), bs_sm = smaddr(Bs);

    auto issue = [&](int s) {
        uint32_t ab = as_sm + (s & 1) * (ATW * 4);
        uint32_t bb = bs_sm + (s & 1) * (BTW * 4);
        int k0w = s * 32;
#pragma unroll
        for (int i = 0; i < 4; i++) {
            int row = crow + i * 32;
            cp16(ab + (row * SAW + coff) * 4, Ag + (size_t)(m0 + row) * KWH + k0w + coff);
        }
#pragma unroll
        for (int i = 0; i < 8; i++) {
            int row = crow + i * 32;
            cp16(bb + (row * SAW + coff) * 4, Bg + (size_t)(n0 + row) * KWH + k0w + coff);
        }
    };

    issue(0);
    CP_COMMIT();

    const int NS = H / 64;
    for (int s = 0; s < NS; s++) {
        if (s > 0) __syncthreads();
        if (s + 1 < NS) {
            issue(s + 1);
            CP_COMMIT();
            CP_WAIT(1);
        } else {
            CP_WAIT(0);
        }
        __syncthreads();

        uint32_t ab = as_sm + (s & 1) * (ATW * 4);
        uint32_t bb = bs_sm + (s & 1) * (BTW * 4);
#pragma unroll
        for (int kw = 0; kw < 32; kw += 8) {
            uint32_t af[4][4];
#pragma unroll
            for (int im = 0; im < 4; im++)
                ldsm4(af[im], ab + ((wm * 64 + im * 16 + (lane & 15)) * SAW + kw) * 4 + (lane >> 4) * 16);
            uint32_t bq[4][4];
#pragma unroll
            for (int p = 0; p < 4; p++)
                ldsm4(bq[p], bb + ((wn * 64 + p * 16 + (lane & 15)) * SAW + kw) * 4 + (lane >> 4) * 16);
#pragma unroll
            for (int im = 0; im < 4; im++)
#pragma unroll
                for (int jn = 0; jn < 8; jn++)
                    mma_bf16(acc[im][jn], af[im], bq[jn >> 1][jn & 1], bq[jn >> 1][(jn & 1) + 2]);
        }
    }

    // epilogue
#pragma unroll
    for (int im = 0; im < 4; im++) {
        int rlo = m0 + wm * 64 + im * 16 + g;
#pragma unroll
        for (int jn = 0; jn < 8; jn++) {
            int n = n0 + wn * 64 + jn * 8 + 2 * t;
            float b0 = bias[n], b1 = bias[n + 1];
#pragma unroll
            for (int h = 0; h < 2; h++) {
                int m = h ? (rlo + 8) : rlo;
                float vx = (h ? acc[im][jn].z : acc[im][jn].x) + b0;
                float vy = (h ? acc[im][jn].w : acc[im][jn].y) + b1;
                if (MODE == 0) {
                    int c = n >> 10;
                    int rem = n & 1023;
                    int hh = rem >> 6;
                    int d = rem & 63;
                    int bb2 = m >> 11;
                    int sIdx = m & 2047;
                    int bh = bb2 * NH + hh;
                    size_t widx = ((size_t)bh * SS + sIdx) * 32 + (d >> 1);
                    if (c == 0)      g_qb[widx] = bf2(vx * QSCALE, vy * QSCALE);
                    else if (c == 1) g_kb[widx] = bf2(vx, vy);
                    else             g_vb[widx] = bf2(vx, vy);
                } else {
                    size_t idx = (size_t)m * H + n;
                    float2 hv = *(const float2*)(resid + idx);
                    *(float2*)(outp + idx) = make_float2(vx + hv.x, vy + hv.y);
                }
            }
        }
    }
}

// ============================================================
// Flash attention: cp.async double-buffered K/V, ldmatrix(.trans for V),
// register-resident P, ex2 softmax. V stays [s][d] everywhere.
// smem words: Qs[128][36], Ks[2][128][36], Vs[2][128][36]  (92160 B)
// warp w owns q-rows [w*16, w*16+16) x full n/d extent.
// ============================================================
#define SQW 36
#define KTW (128 * SQW)     // one K/V stage: 4608 words
#define QW_OFF 0
#define KW_OFF (128 * SQW)
#define VW_OFF (KW_OFF + 2 * KTW)
#define ATTN_SMEM_BYTES ((5 * KTW) * 4)   // 92160 B

__global__ __launch_bounds__(256, 1) void attn_kernel() {
    extern __shared__ uint32_t sm[];
    int tid = threadIdx.x;
    int lane = tid & 31;
    int warp = tid >> 5;
    int g = lane >> 2;
    int t = lane & 3;
    int bh = blockIdx.y;
    int m0 = blockIdx.x * 128;

    const uint32_t* qg = g_qb + (size_t)bh * SS * 32;
    const uint32_t* kg = g_kb + (size_t)bh * SS * 32;
    const uint32_t* vg = g_vb + (size_t)bh * SS * 32;

    uint32_t qs_sm = smaddr(sm + QW_OFF);
    uint32_t ks_sm = smaddr(sm + KW_OFF);
    uint32_t vs_sm = smaddr(sm + VW_OFF);

    // staging map: 2 threads per 32-word row
    int qrow = tid >> 1;
    int qh   = (tid & 1) * 16;

    auto issueKV = [&](int s) {
        uint32_t kb = ks_sm + (s & 1) * (KTW * 4);
        uint32_t vb = vs_sm + (s & 1) * (KTW * 4);
        int kv = s * 128;
        const uint32_t* ksrc = kg + (size_t)(kv + qrow) * 32 + qh;
        const uint32_t* vsrc = vg + (size_t)(kv + qrow) * 32 + qh;
        uint32_t kd = kb + (qrow * SQW + qh) * 4;
        uint32_t vd = vb + (qrow * SQW + qh) * 4;
#pragma unroll
        for (int j = 0; j < 4; j++) {
            cp16(kd + j * 16, ksrc + j * 4);
            cp16(vd + j * 16, vsrc + j * 4);
        }
    };

    // prologue: Q + stage 0 in group 0
    {
        const uint32_t* qsrc = qg + (size_t)(m0 + qrow) * 32 + qh;
        uint32_t qd = qs_sm + (qrow * SQW + qh) * 4;
#pragma unroll
        for (int j = 0; j < 4; j++) cp16(qd + j * 16, qsrc + j * 4);
    }
    issueKV(0);
    CP_COMMIT();

    // hoisted ldmatrix thread coords
    uint32_t lrow = (lane & 15);
    uint32_t lhalf = (lane >> 4) * 16;
    uint32_t q_base = qs_sm + ((warp * 16 + lrow) * SQW) * 4 + lhalf;

    uint32_t af_q[4][4];
    float m0s = -1e30f, m1s = -1e30f;
    float l0 = 0.f, l1 = 0.f;
    float4 oacc[8];
#pragma unroll
    for (int jd = 0; jd < 8; jd++) oacc[jd] = make_float4(0.f, 0.f, 0.f, 0.f);

    const int NS = SS / 128;   // 16
    for (int s = 0; s < NS; s++) {
        if (s > 0) __syncthreads();
        if (s + 1 < NS) {
            issueKV(s + 1);
            CP_COMMIT();
            CP_WAIT(1);
        } else {
            CP_WAIT(0);
        }
        __syncthreads();

        if (s == 0) {
#pragma unroll
            for (int ks = 0; ks < 4; ks++)
                ldsm4(af_q[ks], q_base + ks * 32);
        }

        uint32_t kb = ks_sm + (s & 1) * (KTW * 4) + (lrow * SQW) * 4 + lhalf;
        uint32_t vb = vs_sm + (s & 1) * (KTW * 4) + (lrow * SQW) * 4 + lhalf;

        // S = Q K^T : warp tile m16 x n128, k=64
        float4 sc[16];
#pragma unroll
        for (int jn = 0; jn < 16; jn++) sc[jn] = make_float4(0.f, 0.f, 0.f, 0.f);
#pragma unroll
        for (int ks = 0; ks < 4; ks++) {
            uint32_t bq[8][4];
#pragma unroll
            for (int p = 0; p < 8; p++)
                ldsm4(bq[p], kb + (p * 16 * SQW + ks * 8) * 4);
#pragma unroll
            for (int p = 0; p < 8; p++) {
                mma_bf16(sc[2 * p + 0], af_q[ks], bq[p][0], bq[p][2]);
                mma_bf16(sc[2 * p + 1], af_q[ks], bq[p][1], bq[p][3]);
            }
        }

        // warp-local online softmax (log2 domain, ex2); Q pre-scaled
        float rm0 = -1e30f, rm1 = -1e30f;
#pragma unroll
        for (int jn = 0; jn < 16; jn++) {
            rm0 = fmaxf(rm0, fmaxf(sc[jn].x, sc[jn].y));
            rm1 = fmaxf(rm1, fmaxf(sc[jn].z, sc[jn].w));
        }
        rm0 = fmaxf(rm0, __shfl_xor_sync(0xffffffffu, rm0, 1));
        rm0 = fmaxf(rm0, __shfl_xor_sync(0xffffffffu, rm0, 2));
        rm1 = fmaxf(rm1, __shfl_xor_sync(0xffffffffu, rm1, 1));
        rm1 = fmaxf(rm1, __shfl_xor_sync(0xffffffffu, rm1, 2));
        float nm0 = fmaxf(m0s, rm0), nm1 = fmaxf(m1s, rm1);
        float a0 = ex2(m0s - nm0), a1 = ex2(m1s - nm1);
        m0s = nm0; m1s = nm1;
        float rs0 = 0.f, rs1 = 0.f;
#pragma unroll
        for (int jn = 0; jn < 16; jn++) {
            sc[jn].x = ex2(sc[jn].x - nm0);
            sc[jn].y = ex2(sc[jn].y - nm0);
            sc[jn].z = ex2(sc[jn].z - nm1);
            sc[jn].w = ex2(sc[jn].w - nm1);
            rs0 += sc[jn].x + sc[jn].y;
            rs1 += sc[jn].z + sc[jn].w;
        }
        rs0 += __shfl_xor_sync(0xffffffffu, rs0, 1);
        rs0 += __shfl_xor_sync(0xffffffffu, rs0, 2);
        rs1 += __shfl_xor_sync(0xffffffffu, rs1, 1);
        rs1 += __shfl_xor_sync(0xffffffffu, rs1, 2);
        l0 = l0 * a0 + rs0;
        l1 = l1 * a1 + rs1;
#pragma unroll
        for (int jd = 0; jd < 8; jd++) {
            oacc[jd].x *= a0; oacc[jd].y *= a0;
            oacc[jd].z *= a1; oacc[jd].w *= a1;
        }

        // O += P V : P in registers; V fragments via ldmatrix.trans on [s][d]
#pragma unroll
        for (int ks = 0; ks < 8; ks++) {
            uint32_t ap[4];
            ap[0] = bf2(sc[2 * ks].x, sc[2 * ks].y);
            ap[1] = bf2(sc[2 * ks].z, sc[2 * ks].w);
            ap[2] = bf2(sc[2 * ks + 1].x, sc[2 * ks + 1].y);
            ap[3] = bf2(sc[2 * ks + 1].z, sc[2 * ks + 1].w);
#pragma unroll
            for (int p = 0; p < 4; p++) {
                uint32_t bv[4];
                // rows = s (ks*16 + lrow), col block = d (p*16 elems = p*8 words)
                ldsm4t(bv, vb + (ks * 16 * SQW + p * 8) * 4);
                // trans regs: bv0=(d0-7,k0-7) bv1=(d0-7,k8-15) bv2=(d8-15,k0-7) bv3=(d8-15,k8-15)
                mma_bf16(oacc[2 * p + 0], ap, bv[0], bv[1]);
                mma_bf16(oacc[2 * p + 1], ap, bv[2], bv[3]);
            }
        }
    }

    // finalize -> g_ctxb (bf16x2): ctx[t, hh*64 + d]
    int b = bh >> 4, hh = bh & 15;
    float inv0 = 1.0f / l0, inv1 = 1.0f / l1;
    size_t t0 = (size_t)(b * SS + m0 + warp * 16 + g);
    size_t t1 = t0 + 8;
#pragma unroll
    for (int jd = 0; jd < 8; jd++) {
        int w = hh * 32 + jd * 4 + t;
        g_ctxb[t0 * KWH + w] = bf2(oacc[jd].x * inv0, oacc[jd].y * inv0);
        g_ctxb[t1 * KWH + w] = bf2(oacc[jd].z * inv1, oacc[jd].w * inv1);
    }
}

// ============================================================
extern "C" void kernel_launch(void* const* d_in, const int* in_sizes, int n_in,
                              void* d_out, int out_size) {
    const float* hidden = (const float*)d_in[0];
    const float* gamma  = (const float*)d_in[1];
    const float* beta   = (const float*)d_in[2];
    const float* Wqkv   = (const float*)d_in[3];
    const float* bqkv   = (const float*)d_in[4];
    const float* Wout   = (const float*)d_in[5];
    const float* bout   = (const float*)d_in[6];
    float* out = (float*)d_out;

    tobf<<<(K3 * KWH) / 256, 256>>>(Wqkv, 0, K3 * KWH);
    tobf<<<(H * KWH) / 256, 256>>>(Wout, 1, H * KWH);
    ln_kernel<<<T, 256>>>(hidden, gamma, beta);

    cudaFuncSetAttribute(gemm_bf16<0>, cudaFuncAttributeMaxDynamicSharedMemorySize, GEMM_SMEM);
    cudaFuncSetAttribute(gemm_bf16<1>, cudaFuncAttributeMaxDynamicSharedMemorySize, GEMM_SMEM);
    cudaFuncSetAttribute(attn_kernel, cudaFuncAttributeMaxDynamicSharedMemorySize, ATTN_SMEM_BYTES);

    gemm_bf16<0><<<dim3(K3 / 256, T / 128), 256, GEMM_SMEM>>>(bqkv, nullptr, nullptr);

    attn_kernel<<<dim3(SS / 128, BB * NH), 256, ATTN_SMEM_BYTES>>>();

    gemm_bf16<1><<<dim3(H / 256, T / 128), 256, GEMM_SMEM>>>(bout, hidden, out);
}

// round 12
// speedup vs baseline: 1.4841x; 1.0469x over previous
#include <cuda_runtime.h>
#include <cuda_bf16.h>
#include <cstdint>

#define H  1024
#define NH 16
#define HD 64
#define BB 2
#define SS 2048
#define T  (BB * SS)      // 4096
#define K3 (3 * H)        // 3072
#define KWH 512           // H in bf16x2 words
#define QSCALE 0.18033688f   // 0.125 * log2(e)

// ---- scratch: referenced ONLY from device code (host arg = shadow bug!) ----
__device__ uint32_t g_xnb[(size_t)T * KWH];              // LN out bf16x2
__device__ uint32_t g_wqkv[(size_t)K3 * KWH];            // W_qkv bf16x2
__device__ uint32_t g_wout[(size_t)H * KWH];             // W_out bf16x2
__device__ uint32_t g_qb[(size_t)32 * SS * 32];          // Q bf16x2 [bh][s][d/2], pre-scaled
__device__ uint32_t g_kb[(size_t)32 * SS * 32];          // K bf16x2
__device__ uint32_t g_vb[(size_t)32 * SS * 32];          // V bf16x2
__device__ uint32_t g_ctxb[(size_t)T * KWH];             // ctx bf16x2

// ============================================================
// helpers
// ============================================================
__device__ __forceinline__ uint32_t bf2(float lo, float hi) {
    uint32_t r;
    asm("cvt.rn.bf16x2.f32 %0, %1, %2;" : "=r"(r) : "f"(hi), "f"(lo));
    return r;
}
__device__ __forceinline__ float ex2(float x) {
    float r;
    asm("ex2.approx.f32 %0, %1;" : "=f"(r) : "f"(x));
    return r;
}
__device__ __forceinline__ void mma_bf16(float4& c, const uint32_t a[4], uint32_t b0, uint32_t b1) {
    asm volatile(
        "mma.sync.aligned.m16n8k16.row.col.f32.bf16.bf16.f32 "
        "{%0,%1,%2,%3}, {%4,%5,%6,%7}, {%8,%9}, {%0,%1,%2,%3};"
        : "+f"(c.x), "+f"(c.y), "+f"(c.z), "+f"(c.w)
        : "r"(a[0]), "r"(a[1]), "r"(a[2]), "r"(a[3]), "r"(b0), "r"(b1));
}
__device__ __forceinline__ uint32_t smaddr(const void* p) {
    return (uint32_t)__cvta_generic_to_shared(p);
}
__device__ __forceinline__ void cp16(uint32_t dst, const void* src) {
    asm volatile("cp.async.cg.shared.global [%0], [%1], 16;" :: "r"(dst), "l"(src));
}
#define CP_COMMIT() asm volatile("cp.async.commit_group;")
#define CP_WAIT(n)  asm volatile("cp.async.wait_group %0;" :: "n"(n))
__device__ __forceinline__ void ldsm4(uint32_t* r, uint32_t a) {
    asm volatile("ldmatrix.sync.aligned.m8n8.x4.shared.b16 {%0,%1,%2,%3}, [%4];"
                 : "=r"(r[0]), "=r"(r[1]), "=r"(r[2]), "=r"(r[3]) : "r"(a));
}
__device__ __forceinline__ void ldsm4t(uint32_t* r, uint32_t a) {
    asm volatile("ldmatrix.sync.aligned.m8n8.x4.trans.shared.b16 {%0,%1,%2,%3}, [%4];"
                 : "=r"(r[0]), "=r"(r[1]), "=r"(r[2]), "=r"(r[3]) : "r"(a));
}

// ============================================================
// weight fp32 -> bf16x2
// ============================================================
__global__ __launch_bounds__(256) void tobf(const float* __restrict__ src, int which, int nwords) {
    uint32_t* dst = which ? g_wout : g_wqkv;
    int i = blockIdx.x * 256 + threadIdx.x;
    if (i < nwords) dst[i] = bf2(src[2 * i], src[2 * i + 1]);
}

// ============================================================
// LayerNorm -> bf16x2 words
// ============================================================
__global__ __launch_bounds__(256) void ln_kernel(const float* __restrict__ x,
                                                 const float* __restrict__ gamma,
                                                 const float* __restrict__ beta) {
    int row = blockIdx.x;
    int tid = threadIdx.x;
    float4 v = ((const float4*)(x + (size_t)row * H))[tid];
    float s  = v.x + v.y + v.z + v.w;
    float ss = v.x * v.x + v.y * v.y + v.z * v.z + v.w * v.w;
#pragma unroll
    for (int off = 16; off > 0; off >>= 1) {
        s  += __shfl_xor_sync(0xffffffffu, s, off);
        ss += __shfl_xor_sync(0xffffffffu, ss, off);
    }
    __shared__ float red[16];
    int warp = tid >> 5, lane = tid & 31;
    if (lane == 0) { red[warp] = s; red[8 + warp] = ss; }
    __syncthreads();
    float ts = 0.f, tss = 0.f;
#pragma unroll
    for (int w = 0; w < 8; w++) { ts += red[w]; tss += red[8 + w]; }
    float mu   = ts * (1.0f / H);
    float var  = tss * (1.0f / H) - mu * mu;
    float rstd = rsqrtf(var + 1e-5f);
    float4 g  = ((const float4*)gamma)[tid];
    float4 bt = ((const float4*)beta)[tid];
    float ox = (v.x - mu) * rstd * g.x + bt.x;
    float oy = (v.y - mu) * rstd * g.y + bt.y;
    float oz = (v.z - mu) * rstd * g.z + bt.z;
    float ow = (v.w - mu) * rstd * g.w + bt.w;
    g_xnb[(size_t)row * KWH + tid * 2 + 0] = bf2(ox, oy);
    g_xnb[(size_t)row * KWH + tid * 2 + 1] = bf2(oz, ow);
}

// ============================================================
// Big-warp-tile bf16 GEMM: CTA 128x256, BK=64, 3-buffer cp.async,
// ONE __syncthreads per stage.
// MODE 0: A=g_xnb, B=g_wqkv -> bf16 g_qb (scaled) / g_kb / g_vb
// MODE 1: A=g_ctxb, B=g_wout -> fp32 out (+bias+resid)
// ============================================================
#define SAW 36
#define ATW (128 * SAW)
#define BTW (256 * SAW)
#define GEMM_SMEM ((3 * ATW + 3 * BTW) * 4)   // 165888 B

template <int MODE>
__global__ __launch_bounds__(256, 1) void gemm_bf16(const float* __restrict__ bias,
                                                    const float* __restrict__ resid,
                                                    float* __restrict__ outp) {
    extern __shared__ uint32_t smw[];
    uint32_t* As = smw;                 // [3][ATW]
    uint32_t* Bs = smw + 3 * ATW;       // [3][BTW]
    const uint32_t* Ag = (MODE == 0) ? g_xnb : g_ctxb;
    const uint32_t* Bg = (MODE == 0) ? g_wqkv : g_wout;

    int tid = threadIdx.x;
    int lane = tid & 31;
    int warp = tid >> 5;
    int wm = warp >> 2, wn = warp & 3;
    int g = lane >> 2, t = lane & 3;
    int m0 = blockIdx.y * 128;
    int n0 = blockIdx.x * 256;

    int crow = tid >> 3;
    int coff = (tid & 7) * 4;

    float4 acc[4][8];
#pragma unroll
    for (int i = 0; i < 4; i++)
#pragma unroll
        for (int j = 0; j < 8; j++) acc[i][j] = make_float4(0.f, 0.f, 0.f, 0.f);

    uint32_t as_sm = smaddr(As), bs_sm = smaddr(Bs);

    auto issue = [&](int s) {
        int buf = s % 3;
        uint32_t ab = as_sm + buf * (ATW * 4);
        uint32_t bb = bs_sm + buf * (BTW * 4);
        int k0w = s * 32;
#pragma unroll
        for (int i = 0; i < 4; i++) {
            int row = crow + i * 32;
            cp16(ab + (row * SAW + coff) * 4, Ag + (size_t)(m0 + row) * KWH + k0w + coff);
        }
#pragma unroll
        for (int i = 0; i < 8; i++) {
            int row = crow + i * 32;
            cp16(bb + (row * SAW + coff) * 4, Bg + (size_t)(n0 + row) * KWH + k0w + coff);
        }
    };

    issue(0); CP_COMMIT();
    issue(1); CP_COMMIT();

    const int NS = H / 64;   // 16
    for (int s = 0; s < NS; s++) {
        if (s + 2 < NS) { CP_WAIT(1); } else { CP_WAIT(0); }
        __syncthreads();
        if (s + 2 < NS) { issue(s + 2); CP_COMMIT(); }

        int buf = s % 3;
        uint32_t ab = as_sm + buf * (ATW * 4);
        uint32_t bb = bs_sm + buf * (BTW * 4);
#pragma unroll
        for (int kw = 0; kw < 32; kw += 8) {
            uint32_t af[4][4];
#pragma unroll
            for (int im = 0; im < 4; im++)
                ldsm4(af[im], ab + ((wm * 64 + im * 16 + (lane & 15)) * SAW + kw) * 4 + (lane >> 4) * 16);
            uint32_t bq[4][4];
#pragma unroll
            for (int p = 0; p < 4; p++)
                ldsm4(bq[p], bb + ((wn * 64 + p * 16 + (lane & 15)) * SAW + kw) * 4 + (lane >> 4) * 16);
#pragma unroll
            for (int im = 0; im < 4; im++)
#pragma unroll
                for (int jn = 0; jn < 8; jn++)
                    mma_bf16(acc[im][jn], af[im], bq[jn >> 1][jn & 1], bq[jn >> 1][(jn & 1) + 2]);
        }
    }

    // epilogue
#pragma unroll
    for (int im = 0; im < 4; im++) {
        int rlo = m0 + wm * 64 + im * 16 + g;
#pragma unroll
        for (int jn = 0; jn < 8; jn++) {
            int n = n0 + wn * 64 + jn * 8 + 2 * t;
            float b0 = bias[n], b1 = bias[n + 1];
#pragma unroll
            for (int h = 0; h < 2; h++) {
                int m = h ? (rlo + 8) : rlo;
                float vx = (h ? acc[im][jn].z : acc[im][jn].x) + b0;
                float vy = (h ? acc[im][jn].w : acc[im][jn].y) + b1;
                if (MODE == 0) {
                    int c = n >> 10;
                    int rem = n & 1023;
                    int hh = rem >> 6;
                    int d = rem & 63;
                    int bb2 = m >> 11;
                    int sIdx = m & 2047;
                    int bh = bb2 * NH + hh;
                    size_t widx = ((size_t)bh * SS + sIdx) * 32 + (d >> 1);
                    if (c == 0)      g_qb[widx] = bf2(vx * QSCALE, vy * QSCALE);
                    else if (c == 1) g_kb[widx] = bf2(vx, vy);
                    else             g_vb[widx] = bf2(vx, vy);
                } else {
                    size_t idx = (size_t)m * H + n;
                    float2 hv = *(const float2*)(resid + idx);
                    *(float2*)(outp + idx) = make_float2(vx + hv.x, vy + hv.y);
                }
            }
        }
    }
}

// ============================================================
// Flash attention: 512 threads, split-KV-in-CTA (side = warp>>3 owns
// half the key columns; independent online softmax per side; merged
// once at the end). 3-buffer cp.async K/V, 1 sync/iter, ldmatrix(.trans),
// register-resident P, ex2 softmax.
// smem words: Qs[4608] K[3][4608] V[3][4608] merge[8192] stats[1024]
// ============================================================
#define SQW 36
#define KTW (128 * SQW)              // 4608 words per stage
#define QW_OFF 0
#define KW_OFF KTW
#define VW_OFF (KW_OFF + 3 * KTW)
#define MERGE_OFF (VW_OFF + 3 * KTW) // 7*4608 = 32256
#define STATS_OFF (MERGE_OFF + 8192)
#define ATTN_SMEM_BYTES ((STATS_OFF + 1024) * 4)   // 165888 B

__global__ __launch_bounds__(512, 1) void attn_kernel() {
    extern __shared__ uint32_t sm[];
    int tid = threadIdx.x;
    int lane = tid & 31;
    int warp = tid >> 5;          // 0..15
    int wp = warp & 7;            // q-row group
    int side = warp >> 3;         // 0: cols 0-63, 1: cols 64-127
    int g = lane >> 2;
    int t = lane & 3;
    int bh = blockIdx.y;
    int m0 = blockIdx.x * 128;

    const uint32_t* qg = g_qb + (size_t)bh * SS * 32;
    const uint32_t* kg = g_kb + (size_t)bh * SS * 32;
    const uint32_t* vg = g_vb + (size_t)bh * SS * 32;

    uint32_t qs_sm = smaddr(sm + QW_OFF);
    uint32_t ks_sm = smaddr(sm + KW_OFF);
    uint32_t vs_sm = smaddr(sm + VW_OFF);

    // staging: 4 threads/row, 8 words each
    int srow = tid >> 2;
    int soff = (tid & 3) * 8;

    auto issueKV = [&](int s) {
        int buf = s % 3;
        uint32_t kd = ks_sm + buf * (KTW * 4) + (srow * SQW + soff) * 4;
        uint32_t vd = vs_sm + buf * (KTW * 4) + (srow * SQW + soff) * 4;
        const uint32_t* ksrc = kg + (size_t)(s * 128 + srow) * 32 + soff;
        const uint32_t* vsrc = vg + (size_t)(s * 128 + srow) * 32 + soff;
        cp16(kd, ksrc);       cp16(kd + 16, ksrc + 4);
        cp16(vd, vsrc);       cp16(vd + 16, vsrc + 4);
    };

    // prologue: Q + stage 0 (group 0), stage 1 (group 1)
    {
        uint32_t qd = qs_sm + (srow * SQW + soff) * 4;
        const uint32_t* qsrc = qg + (size_t)(m0 + srow) * 32 + soff;
        cp16(qd, qsrc);       cp16(qd + 16, qsrc + 4);
    }
    issueKV(0); CP_COMMIT();
    issueKV(1); CP_COMMIT();

    uint32_t lrow = (lane & 15);
    uint32_t lhalf = (lane >> 4) * 16;
    uint32_t q_base = qs_sm + ((wp * 16 + lrow) * SQW) * 4 + lhalf;

    uint32_t af_q[4][4];
    float m0s = -1e30f, m1s = -1e30f;
    float l0 = 0.f, l1 = 0.f;
    float4 oacc[8];
#pragma unroll
    for (int jd = 0; jd < 8; jd++) oacc[jd] = make_float4(0.f, 0.f, 0.f, 0.f);

    const int NS = SS / 128;   // 16
    for (int s = 0; s < NS; s++) {
        if (s + 2 < NS) { CP_WAIT(1); } else { CP_WAIT(0); }
        __syncthreads();
        if (s + 2 < NS) { issueKV(s + 2); CP_COMMIT(); }

        if (s == 0) {
#pragma unroll
            for (int ks = 0; ks < 4; ks++)
                ldsm4(af_q[ks], q_base + ks * 32);
        }

        int buf = s % 3;
        uint32_t kb = ks_sm + buf * (KTW * 4) + (lrow * SQW) * 4 + lhalf;
        uint32_t vb = vs_sm + buf * (KTW * 4) + (lrow * SQW) * 4 + lhalf;

        // S = Q K^T : warp tile m16 x n64 (this side's columns), k=64
        float4 sc[8];
#pragma unroll
        for (int jn = 0; jn < 8; jn++) sc[jn] = make_float4(0.f, 0.f, 0.f, 0.f);
#pragma unroll
        for (int ks = 0; ks < 4; ks++) {
            uint32_t bq[4][4];
#pragma unroll
            for (int p = 0; p < 4; p++)
                ldsm4(bq[p], kb + ((side * 64 + p * 16) * SQW + ks * 8) * 4);
#pragma unroll
            for (int p = 0; p < 4; p++) {
                mma_bf16(sc[2 * p + 0], af_q[ks], bq[p][0], bq[p][2]);
                mma_bf16(sc[2 * p + 1], af_q[ks], bq[p][1], bq[p][3]);
            }
        }

        // side-local online softmax (log2 domain, ex2); Q pre-scaled
        float rm0 = -1e30f, rm1 = -1e30f;
#pragma unroll
        for (int jn = 0; jn < 8; jn++) {
            rm0 = fmaxf(rm0, fmaxf(sc[jn].x, sc[jn].y));
            rm1 = fmaxf(rm1, fmaxf(sc[jn].z, sc[jn].w));
        }
        rm0 = fmaxf(rm0, __shfl_xor_sync(0xffffffffu, rm0, 1));
        rm0 = fmaxf(rm0, __shfl_xor_sync(0xffffffffu, rm0, 2));
        rm1 = fmaxf(rm1, __shfl_xor_sync(0xffffffffu, rm1, 1));
        rm1 = fmaxf(rm1, __shfl_xor_sync(0xffffffffu, rm1, 2));
        float nm0 = fmaxf(m0s, rm0), nm1 = fmaxf(m1s, rm1);
        float a0 = ex2(m0s - nm0), a1 = ex2(m1s - nm1);
        m0s = nm0; m1s = nm1;
        float rs0 = 0.f, rs1 = 0.f;
#pragma unroll
        for (int jn = 0; jn < 8; jn++) {
            sc[jn].x = ex2(sc[jn].x - nm0);
            sc[jn].y = ex2(sc[jn].y - nm0);
            sc[jn].z = ex2(sc[jn].z - nm1);
            sc[jn].w = ex2(sc[jn].w - nm1);
            rs0 += sc[jn].x + sc[jn].y;
            rs1 += sc[jn].z + sc[jn].w;
        }
        rs0 += __shfl_xor_sync(0xffffffffu, rs0, 1);
        rs0 += __shfl_xor_sync(0xffffffffu, rs0, 2);
        rs1 += __shfl_xor_sync(0xffffffffu, rs1, 1);
        rs1 += __shfl_xor_sync(0xffffffffu, rs1, 2);
        l0 = l0 * a0 + rs0;
        l1 = l1 * a1 + rs1;
#pragma unroll
        for (int jd = 0; jd < 8; jd++) {
            oacc[jd].x *= a0; oacc[jd].y *= a0;
            oacc[jd].z *= a1; oacc[jd].w *= a1;
        }

        // O += P V over this side's 64 keys (4 k16 steps), V via ldsm.trans
#pragma unroll
        for (int ks = 0; ks < 4; ks++) {
            uint32_t ap[4];
            ap[0] = bf2(sc[2 * ks].x, sc[2 * ks].y);
            ap[1] = bf2(sc[2 * ks].z, sc[2 * ks].w);
            ap[2] = bf2(sc[2 * ks + 1].x, sc[2 * ks + 1].y);
            ap[3] = bf2(sc[2 * ks + 1].z, sc[2 * ks + 1].w);
#pragma unroll
            for (int p = 0; p < 4; p++) {
                uint32_t bv[4];
                ldsm4t(bv, vb + ((side * 64 + ks * 16) * SQW + p * 8) * 4);
                mma_bf16(oacc[2 * p + 0], ap, bv[0], bv[1]);
                mma_bf16(oacc[2 * p + 1], ap, bv[2], bv[3]);
            }
        }
    }

    // ---- merge the two sides (flash split-KV merge) ----
    float4* mbuf = (float4*)(sm + MERGE_OFF);
    float4* sbuf = (float4*)(sm + STATS_OFF);
    if (side == 1) {
        int t2 = tid - 256;
#pragma unroll
        for (int jd = 0; jd < 8; jd++) mbuf[t2 * 8 + jd] = oacc[jd];
        sbuf[t2] = make_float4(m0s, m1s, l0, l1);
    }
    __syncthreads();
    if (side == 0) {
        float4 ps = sbuf[tid];
        float nm0 = fmaxf(m0s, ps.x), nm1 = fmaxf(m1s, ps.y);
        float sA0 = ex2(m0s - nm0), sB0 = ex2(ps.x - nm0);
        float sA1 = ex2(m1s - nm1), sB1 = ex2(ps.y - nm1);
        float inv0 = 1.0f / (l0 * sA0 + ps.z * sB0);
        float inv1 = 1.0f / (l1 * sA1 + ps.w * sB1);

        int b = bh >> 4, hh = bh & 15;
        size_t t0 = (size_t)(b * SS + m0 + wp * 16 + g);
        size_t t1 = t0 + 8;
#pragma unroll
        for (int jd = 0; jd < 8; jd++) {
            float4 ob = mbuf[tid * 8 + jd];
            float x0 = (oacc[jd].x * sA0 + ob.x * sB0) * inv0;
            float y0 = (oacc[jd].y * sA0 + ob.y * sB0) * inv0;
            float x1 = (oacc[jd].z * sA1 + ob.z * sB1) * inv1;
            float y1 = (oacc[jd].w * sA1 + ob.w * sB1) * inv1;
            int w = hh * 32 + jd * 4 + t;
            g_ctxb[t0 * KWH + w] = bf2(x0, y0);
            g_ctxb[t1 * KWH + w] = bf2(x1, y1);
        }
    }
}

// ============================================================
extern "C" void kernel_launch(void* const* d_in, const int* in_sizes, int n_in,
                              void* d_out, int out_size) {
    const float* hidden = (const float*)d_in[0];
    const float* gamma  = (const float*)d_in[1];
    const float* beta   = (const float*)d_in[2];
    const float* Wqkv   = (const float*)d_in[3];
    const float* bqkv   = (const float*)d_in[4];
    const float* Wout   = (const float*)d_in[5];
    const float* bout   = (const float*)d_in[6];
    float* out = (float*)d_out;

    tobf<<<(K3 * KWH) / 256, 256>>>(Wqkv, 0, K3 * KWH);
    tobf<<<(H * KWH) / 256, 256>>>(Wout, 1, H * KWH);
    ln_kernel<<<T, 256>>>(hidden, gamma, beta);

    cudaFuncSetAttribute(gemm_bf16<0>, cudaFuncAttributeMaxDynamicSharedMemorySize, GEMM_SMEM);
    cudaFuncSetAttribute(gemm_bf16<1>, cudaFuncAttributeMaxDynamicSharedMemorySize, GEMM_SMEM);
    cudaFuncSetAttribute(attn_kernel, cudaFuncAttributeMaxDynamicSharedMemorySize, ATTN_SMEM_BYTES);

    gemm_bf16<0><<<dim3(K3 / 256, T / 128), 256, GEMM_SMEM>>>(bqkv, nullptr, nullptr);

    attn_kernel<<<dim3(SS / 128, BB * NH), 512, ATTN_SMEM_BYTES>>>();

    gemm_bf16<1><<<dim3(H / 256, T / 128), 256, GEMM_SMEM>>>(bout, hidden, out);
}